// round 8
// baseline (speedup 1.0000x reference)
#include <cuda_runtime.h>
#include <cuda_fp16.h>
#include <math.h>
#include <cstdint>

// ---------------------------------------------------------------------------
// MSMDDeformRegionAttn  (N=4, Lq=300, C=256, H=8, Dh=32, L=4, P=4, ROI=7)
//
//   1. value = input_flatten @ Wv + bv            (79788 x 256 x 256)  HMMA
//   2. ROI-align 7x7 on level-0 feature map -> roi planes (fp16 split)
//   3. pw = roi_flat @ [Wp | Ww]                  (1200 x 12544 x 384) HMMA
//   4. tanh offsets + softmax weights + deformable bilinear gather
//   5. out = att @ Wo + bo                        (1200 x 256 x 256)   HMMA
//
// All GEMMs: mma.sync m16n8k16 fp16 (baseline PTX) with 2-way fp16 split of
// each fp32 operand and 3 cross-products (00, 01, 10) -> residual ~2^-22.
// Weights pre-scaled x64 so residual terms stay in fp16 normal range;
// epilogue multiplies by 1/64. 3-stage cp.async pipeline, swizzled smem.
// ---------------------------------------------------------------------------

#define NBATCH  4
#define LQ      300
#define NQ      (NBATCH * LQ)      // 1200
#define CDIM    256
#define NHEADS  8
#define DH      32
#define NLVL    4
#define NPTS    4
#define ROI     7
#define LEN_IN  19947
#define ROI_DIM (ROI * ROI * CDIM) // 12544
#define NPW     384                // 256 (Wp) + 128 (Ww)
#define SPLITK  28
#define KCHUNK  (ROI_DIM / SPLITK) // 448 = 14 * 32
#define MV      (NBATCH * LEN_IN)  // 79788
#define MVPAD   79872              // 624 * 128
#define NQPAD   1280               // 10 * 128
#define WSCALE  64.0f
#define WSCALE_INV (1.0f / 64.0f)

// ------------------------- scratch (static device mem) ---------------------
__device__ float  g_value[(size_t)MV * CDIM];                  // 81.7 MB
__device__ __half g_aspl[(size_t)2 * MVPAD * CDIM];            // 81.8 MB
__device__ __half g_roiA[(size_t)2 * NQPAD * ROI_DIM];         // 64.2 MB
__device__ __half g_attA[(size_t)2 * NQPAD * CDIM];            //  1.3 MB
__device__ float  g_part[(size_t)SPLITK * NQ * NPW];           // 51.6 MB
__device__ float  g_pw[(size_t)NQ * NPW];
__device__ __half g_btv[(size_t)2 * CDIM * CDIM];
__device__ __half g_btpw[(size_t)2 * NPW * ROI_DIM];           // 19.3 MB
__device__ __half g_btwo[(size_t)2 * CDIM * CDIM];

// --------------------------- PTX primitives --------------------------------
__device__ __forceinline__ uint32_t smem_u32(const void* p)
{
    uint32_t a;
    asm("{ .reg .u64 t; cvta.to.shared.u64 t, %1; cvt.u32.u64 %0, t; }"
        : "=r"(a) : "l"(p));
    return a;
}
__device__ __forceinline__ void cp16(uint32_t dst, const void* src)
{
    asm volatile("cp.async.cg.shared.global [%0], [%1], 16;"
                 :: "r"(dst), "l"(src));
}
__device__ __forceinline__ void mma_f16(float* d, const uint32_t* a,
                                        const uint32_t* b)
{
    asm volatile(
        "mma.sync.aligned.m16n8k16.row.col.f32.f16.f16.f32 "
        "{%0,%1,%2,%3}, {%4,%5,%6,%7}, {%8,%9}, {%0,%1,%2,%3};"
        : "+f"(d[0]), "+f"(d[1]), "+f"(d[2]), "+f"(d[3])
        : "r"(a[0]), "r"(a[1]), "r"(a[2]), "r"(a[3]), "r"(b[0]), "r"(b[1]));
}
__device__ __forceinline__ void ldsm4(uint32_t* r, uint32_t addr)
{
    asm volatile(
        "ldmatrix.sync.aligned.m8n8.x4.shared.b16 {%0,%1,%2,%3}, [%4];"
        : "=r"(r[0]), "=r"(r[1]), "=r"(r[2]), "=r"(r[3]) : "r"(addr));
}

// --------------------------- fp16 2-way split -------------------------------
__device__ __forceinline__ void h2split(float x, __half& h0, __half& h1)
{
    h0 = __float2half_rn(x);
    h1 = __float2half_rn(x - __half2float(h0));
}

// ------------------------- fp16x2 HMMA GEMM ---------------------------------
// C = (A @ B^T) * outScale + bias, logical fp32 via 2-plane fp16 operands.
// A planes: Ap[p][m][k] (plane stride aPlane, row stride lda), m padded to 128.
// B planes: Bp[p][n][k] (plane stride bPlane, row stride ldb), n mult of 128.
// Block tile 128x128, BK=32, 8 warps (2x4), warp tile 64x32.
// 3-stage cp.async pipeline (two groups in flight during compute).
// Swizzled smem: row r (64B of 32 fp16), chunk c (16B): c' = c ^ ((r>>1)&3).
#define BUFB 32768   // bytes per stage: A 2*8192 + B 2*8192
#define NSTAGE 3
#define SMEM_TOT (NSTAGE * BUFB)   // 98304

__global__ __launch_bounds__(256, 2) void mma_gemm(
    const __half* __restrict__ Ap, size_t aPlane, int lda,
    const __half* __restrict__ Bp, size_t bPlane, int ldb,
    float* __restrict__ C, int ldc, long long cSplitStride,
    int M, int kChunkTot, const float* __restrict__ bias, float outScale)
{
    extern __shared__ __align__(16) char smc[];
    const uint32_t sb = smem_u32(smc);
    const int tid = threadIdx.x, lane = tid & 31, wid = tid >> 5;
    const int warp_m = wid >> 2, warp_n = wid & 3;
    const int m0 = blockIdx.y * 128, n0 = blockIdx.x * 128;
    const int kBase = blockIdx.z * kChunkTot;
    C += (long long)blockIdx.z * cSplitStride;

    // cp.async coordinates: thread t -> rows lr, lr+64; 16B chunk lc
    const int lr = tid >> 2, lc = tid & 3;
    const uint32_t swz = (uint32_t)(lc ^ ((lr >> 1) & 3)) << 4;
    const uint32_t d1 = (uint32_t)lr * 64 + swz;
    const uint32_t d2 = d1 + 64 * 64;
    const __half* aS = Ap + (size_t)(m0 + lr) * lda + kBase + lc * 8;
    const __half* bS = Bp + (size_t)(n0 + lr) * ldb + kBase + lc * 8;

#define ISSUE(bo, ke)                                                          \
    do {                                                                       \
        cp16(sb + (bo) + d1, aS + (ke));                                       \
        cp16(sb + (bo) + 8192 + d1, aS + aPlane + (ke));                       \
        cp16(sb + (bo) + d2, aS + (size_t)64 * lda + (ke));                    \
        cp16(sb + (bo) + 8192 + d2, aS + aPlane + (size_t)64 * lda + (ke));    \
        cp16(sb + (bo) + 16384 + d1, bS + (ke));                               \
        cp16(sb + (bo) + 24576 + d1, bS + bPlane + (ke));                      \
        cp16(sb + (bo) + 16384 + d2, bS + (size_t)64 * ldb + (ke));            \
        cp16(sb + (bo) + 24576 + d2, bS + bPlane + (size_t)64 * ldb + (ke));   \
        asm volatile("cp.async.commit_group;" ::: "memory");                   \
    } while (0)

    // ldmatrix coordinates
    const uint32_t aRow = (uint32_t)(warp_m * 64 + (lane & 15));
    const uint32_t aOff = aRow * 64;
    const uint32_t aSwz = (aRow >> 1) & 3;
    const uint32_t aCk = (uint32_t)(lane >> 4);           // 0/1
    const uint32_t bRow = (uint32_t)(warp_n * 32 + ((lane >> 4) << 3) + (lane & 7));
    const uint32_t bOff = bRow * 64;
    const uint32_t bSwz = (bRow >> 1) & 3;
    const uint32_t bCk = (uint32_t)((lane >> 3) & 1);

    float acc[4][4][4];
#pragma unroll
    for (int i = 0; i < 4; i++)
#pragma unroll
        for (int j = 0; j < 4; j++)
#pragma unroll
            for (int e = 0; e < 4; e++) acc[i][j][e] = 0.f;

    const int nIter = kChunkTot / 32;
    // prologue: stages 0 and 1 in flight
    ISSUE(0u, 0);
    if (nIter > 1) ISSUE((uint32_t)BUFB, 32);

    uint32_t bo = 0;
    for (int it = 0; it < nIter; it++) {
        // group 'it' must be complete; keep group 'it+1' in flight
        if (it < nIter - 1) {
            asm volatile("cp.async.wait_group 1;" ::: "memory");
        } else {
            asm volatile("cp.async.wait_group 0;" ::: "memory");
        }
        __syncthreads();   // data visible + prior reads of buffer (it+2)%3 done
        if (it + 2 < nIter) {
            const uint32_t nbo = (uint32_t)(((it + 2) % NSTAGE) * BUFB);
            ISSUE(nbo, (it + 2) * 32);
        }

        // compute buffer bo: 2 k16 steps x 3 plane-products x 16 mma
#pragma unroll
        for (int h = 0; h < 2; h++) {
            uint32_t bfr[2][4][2];
#pragma unroll
            for (int pb = 0; pb < 2; pb++)
#pragma unroll
                for (int jj = 0; jj < 2; jj++) {
                    uint32_t r[4];
                    ldsm4(r, sb + bo + 16384 + pb * 8192 + bOff + jj * 1024 +
                             ((((uint32_t)(h * 2) + bCk) ^ bSwz) << 4));
                    bfr[pb][jj * 2][0] = r[0]; bfr[pb][jj * 2][1] = r[1];
                    bfr[pb][jj * 2 + 1][0] = r[2]; bfr[pb][jj * 2 + 1][1] = r[3];
                }
#pragma unroll
            for (int pa = 0; pa < 2; pa++) {
                uint32_t af[4][4];
#pragma unroll
                for (int i = 0; i < 4; i++)
                    ldsm4(af[i], sb + bo + pa * 8192 + aOff + i * 1024 +
                                 ((((uint32_t)(h * 2) + aCk) ^ aSwz) << 4));
                const int npb = 2 - pa;   // pa=0: pb 0,1 ; pa=1: pb 0
                for (int pb = 0; pb < npb; pb++)
#pragma unroll
                    for (int i = 0; i < 4; i++)
#pragma unroll
                        for (int j = 0; j < 4; j++)
                            mma_f16(acc[i][j], af[i], bfr[pb][j]);
            }
        }
        bo += (uint32_t)BUFB;
        if (bo == (uint32_t)SMEM_TOT) bo = 0;
    }
#undef ISSUE

    // epilogue
    const int colBase = n0 + warp_n * 32 + (lane & 3) * 2;
    const int rowBase = m0 + warp_m * 64 + (lane >> 2);
#pragma unroll
    for (int i = 0; i < 4; i++) {
#pragma unroll
        for (int j = 0; j < 4; j++) {
            const int gc = colBase + j * 8;
            float bx = 0.f, by = 0.f;
            if (bias) { bx = bias[gc]; by = bias[gc + 1]; }
            const int r0 = rowBase + i * 16;
            if (r0 < M) {
                float2 v = make_float2(acc[i][j][0] * outScale + bx,
                                       acc[i][j][1] * outScale + by);
                *(float2*)(C + (size_t)r0 * ldc + gc) = v;
            }
            const int r1 = r0 + 8;
            if (r1 < M) {
                float2 v = make_float2(acc[i][j][2] * outScale + bx,
                                       acc[i][j][3] * outScale + by);
                *(float2*)(C + (size_t)r1 * ldc + gc) = v;
            }
        }
    }
}

// -------------- weight transpose + scale(x64) + fp16 2-way split ------------
// W is [K][N] fp32; out planes are [Ntot][K] fp16, rows offset by rowOff.
__global__ __launch_bounds__(256) void k_tsplit(
    const float* __restrict__ W, int K, int N,
    __half* __restrict__ out, size_t plane, int rowOff)
{
    __shared__ float t[32][33];
    const int kb = blockIdx.y * 32, nb = blockIdx.x * 32;
    const int c = threadIdx.x & 31, r8 = threadIdx.x >> 5;
#pragma unroll
    for (int i = 0; i < 4; i++)
        t[r8 + i * 8][c] = W[(size_t)(kb + r8 + i * 8) * N + nb + c];
    __syncthreads();
#pragma unroll
    for (int i = 0; i < 4; i++) {
        const int n = nb + r8 + i * 8;
        const int k = kb + c;
        float x = t[c][r8 + i * 8] * WSCALE;
        __half h0, h1;
        h2split(x, h0, h1);
        size_t o = (size_t)(n + rowOff) * K + k;
        out[o] = h0;
        out[plane + o] = h1;
    }
}

// -------------------- A-operand fp16 2-way split (elementwise) --------------
__global__ __launch_bounds__(256) void k_asplit(
    const float* __restrict__ in, __half* __restrict__ out, size_t plane, int n4)
{
    int i = blockIdx.x * 256 + threadIdx.x;
    if (i >= n4) return;
    float4 v = ((const float4*)in)[i];
    float f[4] = {v.x, v.y, v.z, v.w};
    uint32_t p0[2], p1[2];
#pragma unroll
    for (int e = 0; e < 2; e++) {
        __half a0, a1, b0, b1;
        h2split(f[e * 2], a0, a1);
        h2split(f[e * 2 + 1], b0, b1);
        p0[e] = (uint32_t)__half_as_ushort(a0) |
                ((uint32_t)__half_as_ushort(b0) << 16);
        p1[e] = (uint32_t)__half_as_ushort(a1) |
                ((uint32_t)__half_as_ushort(b1) << 16);
    }
    *(uint2*)(out + (size_t)i * 4) = make_uint2(p0[0], p0[1]);
    *(uint2*)(out + plane + (size_t)i * 4) = make_uint2(p1[0], p1[1]);
}

// --------------------------- bilinear helper -------------------------------
__device__ __forceinline__ float bilin(const float* __restrict__ base,
                                       int Hl, int Wl, int stride,
                                       float y, float x)
{
    float fy = floorf(y), fx = floorf(x);
    int y0 = (int)fy, x0 = (int)fx;
    float wy1 = y - fy, wx1 = x - fx;
    float wy0 = 1.f - wy1, wx0 = 1.f - wx1;
    float v = 0.f;
    bool xa = (x0 >= 0) && (x0 < Wl);
    bool xb = (x0 + 1 >= 0) && (x0 + 1 < Wl);
    if (y0 >= 0 && y0 < Hl) {
        if (xa) v += base[(y0 * Wl + x0) * stride] * (wy0 * wx0);
        if (xb) v += base[(y0 * Wl + x0 + 1) * stride] * (wy0 * wx1);
    }
    if (y0 + 1 >= 0 && y0 + 1 < Hl) {
        if (xa) v += base[((y0 + 1) * Wl + x0) * stride] * (wy1 * wx0);
        if (xb) v += base[((y0 + 1) * Wl + x0 + 1) * stride] * (wy1 * wx1);
    }
    return v;
}

// ------------------- ROI align -> split fp16 planes -------------------------
__global__ __launch_bounds__(256) void k_roi(const float* __restrict__ ref,
                                             const float* __restrict__ value,
                                             __half* __restrict__ roiA)
{
    int q = blockIdx.x;
    int n = q / LQ;
    int t = threadIdx.x;
    __shared__ float sr[4];
    if (t < 4) sr[t] = ref[(size_t)q * 16 + t];
    __syncthreads();
    const float cx = sr[0], cy = sr[1], w = sr[2], h = sr[3];
    const float x1 = (cx - 0.5f * w) * 150.f - 0.5f;
    const float y1 = (cy - 0.5f * h) * 100.f - 0.5f;
    const float bw = w * 150.f / (float)ROI;
    const float bh = h * 100.f / (float)ROI;
    const float* base = value + (size_t)n * LEN_IN * CDIM + t;
    __half* out0 = roiA + (size_t)q * ROI_DIM;
    __half* out1 = out0 + (size_t)NQPAD * ROI_DIM;
    for (int by = 0; by < ROI; by++) {
        float y = y1 + bh * ((float)by + 0.5f);
        for (int bx = 0; bx < ROI; bx++) {
            float x = x1 + bw * ((float)bx + 0.5f);
            float v = bilin(base, 100, 150, CDIM, y, x);
            __half h0, h1;
            h2split(v, h0, h1);
            out0[(by * ROI + bx) * CDIM + t] = h0;
            out1[(by * ROI + bx) * CDIM + t] = h1;
        }
    }
}

// ------------------------- split-K reduce + bias ----------------------------
__global__ __launch_bounds__(256) void k_reduce(const float* __restrict__ part,
                                                const float* __restrict__ bp,
                                                const float* __restrict__ bw,
                                                float* __restrict__ pw)
{
    int i = blockIdx.x * 256 + threadIdx.x;
    if (i >= NQ * NPW) return;
    int j = i % NPW;
    float s = (j < 256) ? bp[j] : bw[j - 256];
#pragma unroll
    for (int z = 0; z < SPLITK; z++) s += part[(size_t)z * NQ * NPW + i];
    pw[i] = s;
}

// -------- deformable sampling + weighted sum -> split fp16 att planes -------
__global__ __launch_bounds__(256) void k_sample(const float* __restrict__ ref,
                                                const float* __restrict__ pw,
                                                const float* __restrict__ value,
                                                __half* __restrict__ attA)
{
    int q = blockIdx.x;
    int n = q / LQ;
    int t = threadIdx.x;
    int h = t >> 5, d = t & 31;
    __shared__ float s_px[NHEADS][16];
    __shared__ float s_py[NHEADS][16];
    __shared__ float s_w[NHEADS][16];
    __shared__ float s_ref[16];
    if (t < 16) s_ref[t] = ref[(size_t)q * 16 + t];
    __syncthreads();
    const float* row = pw + (size_t)q * NPW;
    if (t < 128) {
        int hh = t >> 4, lp = t & 15, l = lp >> 2;
        float ox = tanhf(row[2 * t]);
        float oy = tanhf(row[2 * t + 1]);
        s_px[hh][lp] = s_ref[l * 4 + 0] + ox * s_ref[l * 4 + 2] * 0.5f;
        s_py[hh][lp] = s_ref[l * 4 + 1] + oy * s_ref[l * 4 + 3] * 0.5f;
        s_w[hh][lp] = row[256 + t];
    }
    __syncthreads();
    if (t < NHEADS) {
        float mx = -1e30f;
#pragma unroll
        for (int i = 0; i < 16; i++) mx = fmaxf(mx, s_w[t][i]);
        float sum = 0.f;
#pragma unroll
        for (int i = 0; i < 16; i++) {
            float e = expf(s_w[t][i] - mx);
            s_w[t][i] = e;
            sum += e;
        }
        float inv = 1.f / sum;
#pragma unroll
        for (int i = 0; i < 16; i++) s_w[t][i] *= inv;
    }
    __syncthreads();
    const int HL[4] = {100, 50, 25, 13};
    const int WL[4] = {150, 75, 38, 19};
    const int SL[4] = {0, 15000, 18750, 19700};
    float acc = 0.f;
#pragma unroll
    for (int l = 0; l < NLVL; l++) {
        const float* base =
            value + ((size_t)n * LEN_IN + SL[l]) * CDIM + h * DH + d;
#pragma unroll
        for (int p = 0; p < NPTS; p++) {
            int lp = l * 4 + p;
            float px = s_px[h][lp] * (float)WL[l] - 0.5f;
            float py = s_py[h][lp] * (float)HL[l] - 0.5f;
            acc += s_w[h][lp] * bilin(base, HL[l], WL[l], CDIM, py, px);
        }
    }
    __half h0, h1;
    h2split(acc, h0, h1);
    attA[(size_t)q * CDIM + t] = h0;
    attA[(size_t)NQPAD * CDIM + (size_t)q * CDIM + t] = h1;
}

// ------------------------------ launcher -----------------------------------
extern "C" void kernel_launch(void* const* d_in, const int* in_sizes, int n_in,
                              void* d_out, int out_size)
{
    (void)in_sizes; (void)n_in; (void)out_size;
    const float* ref  = (const float*)d_in[1];
    const float* flat = (const float*)d_in[2];
    const float* Wv   = (const float*)d_in[6];
    const float* bv   = (const float*)d_in[7];
    const float* Wp   = (const float*)d_in[8];
    const float* bp   = (const float*)d_in[9];
    const float* Ww   = (const float*)d_in[10];
    const float* bw   = (const float*)d_in[11];
    const float* Wo   = (const float*)d_in[12];
    const float* bo   = (const float*)d_in[13];
    float* out = (float*)d_out;

    float *p_value, *p_part, *p_pw;
    __half *p_aspl, *p_roiA, *p_attA, *p_btv, *p_btpw, *p_btwo;
    cudaGetSymbolAddress((void**)&p_value, g_value);
    cudaGetSymbolAddress((void**)&p_aspl,  g_aspl);
    cudaGetSymbolAddress((void**)&p_roiA,  g_roiA);
    cudaGetSymbolAddress((void**)&p_attA,  g_attA);
    cudaGetSymbolAddress((void**)&p_part,  g_part);
    cudaGetSymbolAddress((void**)&p_pw,    g_pw);
    cudaGetSymbolAddress((void**)&p_btv,   g_btv);
    cudaGetSymbolAddress((void**)&p_btpw,  g_btpw);
    cudaGetSymbolAddress((void**)&p_btwo,  g_btwo);

    cudaFuncSetAttribute(mma_gemm, cudaFuncAttributeMaxDynamicSharedMemorySize,
                         SMEM_TOT);

    // 0. weight transpose + x64 scale + fp16 split
    k_tsplit<<<dim3(CDIM / 32, CDIM / 32), 256>>>(
        Wv, CDIM, CDIM, p_btv, (size_t)CDIM * CDIM, 0);
    k_tsplit<<<dim3(256 / 32, ROI_DIM / 32), 256>>>(
        Wp, ROI_DIM, 256, p_btpw, (size_t)NPW * ROI_DIM, 0);
    k_tsplit<<<dim3(128 / 32, ROI_DIM / 32), 256>>>(
        Ww, ROI_DIM, 128, p_btpw, (size_t)NPW * ROI_DIM, 256);
    k_tsplit<<<dim3(CDIM / 32, CDIM / 32), 256>>>(
        Wo, CDIM, CDIM, p_btwo, (size_t)CDIM * CDIM, 0);

    // 0b. split input_flatten into fp16 planes
    const int n4 = MV * CDIM / 4;
    k_asplit<<<(n4 + 255) / 256, 256>>>(flat, p_aspl,
                                        (size_t)MVPAD * CDIM, n4);

    // 1. value = input_flatten @ Wv + bv   (grid 2 x 624)
    mma_gemm<<<dim3(CDIM / 128, MVPAD / 128, 1), 256, SMEM_TOT>>>(
        p_aspl, (size_t)MVPAD * CDIM, CDIM,
        p_btv, (size_t)CDIM * CDIM, CDIM,
        p_value, CDIM, 0, MV, CDIM, bv, WSCALE_INV);

    // 2. ROI align -> split fp16 roi planes
    k_roi<<<NQ, 256>>>(ref, p_value, p_roiA);

    // 3. pw partials: roi @ [Wp | Ww]  (grid 3 x 10 x 28)
    mma_gemm<<<dim3(NPW / 128, NQPAD / 128, SPLITK), 256, SMEM_TOT>>>(
        p_roiA, (size_t)NQPAD * ROI_DIM, ROI_DIM,
        p_btpw, (size_t)NPW * ROI_DIM, ROI_DIM,
        p_part, NPW, (long long)NQ * NPW, NQ, KCHUNK, nullptr, WSCALE_INV);
    k_reduce<<<(NQ * NPW + 255) / 256, 256>>>(p_part, bp, bw, p_pw);

    // 4. deformable sampling -> split fp16 att planes
    k_sample<<<NQ, 256>>>(ref, p_pw, p_value, p_attA);

    // 5. out = att @ Wo + bo  (grid 2 x 10)
    mma_gemm<<<dim3(CDIM / 128, NQPAD / 128, 1), 256, SMEM_TOT>>>(
        p_attA, (size_t)NQPAD * CDIM, CDIM,
        p_btwo, (size_t)CDIM * CDIM, CDIM,
        out, CDIM, 0, NQ, CDIM, bo, WSCALE_INV);
}

// round 9
// speedup vs baseline: 1.0208x; 1.0208x over previous
#include <cuda_runtime.h>
#include <cuda_fp16.h>
#include <math.h>
#include <cstdint>

// ---------------------------------------------------------------------------
// MSMDDeformRegionAttn  (N=4, Lq=300, C=256, H=8, Dh=32, L=4, P=4, ROI=7)
//
//   1. value = input_flatten @ Wv + bv            (79788 x 256 x 256)  HMMA
//      (A-operand fp32 -> fp16x2 split fused into the GEMM A-load)
//   2. ROI-align 7x7 on level-0 feature map -> roi planes (fp16 split)
//   3. pw = roi_flat @ [Wp | Ww]                  (1200 x 12544 x 384) HMMA
//   4. tanh offsets + softmax weights + deformable bilinear gather
//   5. out = att @ Wo + bo                        (1200 x 256 x 256)   HMMA
//
// All GEMMs: mma.sync m16n8k16 fp16 with 2-way fp16 split of each fp32
// operand and 3 cross-products (00, 01, 10) -> residual ~2^-22. Weights
// pre-scaled x64 (epilogue x 1/64) to keep residuals in fp16 normal range.
// ---------------------------------------------------------------------------

#define NBATCH  4
#define LQ      300
#define NQ      (NBATCH * LQ)      // 1200
#define CDIM    256
#define NHEADS  8
#define DH      32
#define NLVL    4
#define NPTS    4
#define ROI     7
#define LEN_IN  19947
#define ROI_DIM (ROI * ROI * CDIM) // 12544
#define NPW     384                // 256 (Wp) + 128 (Ww)
#define SPLITK  28
#define KCHUNK  (ROI_DIM / SPLITK) // 448 = 14 * 32
#define MV      (NBATCH * LEN_IN)  // 79788
#define NQPAD   1280               // 10 * 128
#define WSCALE  64.0f
#define WSCALE_INV (1.0f / 64.0f)

// ------------------------- scratch (static device mem) ---------------------
__device__ float  g_value[(size_t)MV * CDIM];                  // 81.7 MB
__device__ __half g_roiA[(size_t)2 * NQPAD * ROI_DIM];         // 64.2 MB
__device__ __half g_attA[(size_t)2 * NQPAD * CDIM];            //  1.3 MB
__device__ float  g_part[(size_t)SPLITK * NQ * NPW];           // 51.6 MB
__device__ float  g_pw[(size_t)NQ * NPW];
__device__ __half g_btv[(size_t)2 * CDIM * CDIM];
__device__ __half g_btpw[(size_t)2 * NPW * ROI_DIM];           // 19.3 MB
__device__ __half g_btwo[(size_t)2 * CDIM * CDIM];

// --------------------------- PTX primitives --------------------------------
__device__ __forceinline__ uint32_t smem_u32(const void* p)
{
    uint32_t a;
    asm("{ .reg .u64 t; cvta.to.shared.u64 t, %1; cvt.u32.u64 %0, t; }"
        : "=r"(a) : "l"(p));
    return a;
}
__device__ __forceinline__ void cp16(uint32_t dst, const void* src)
{
    asm volatile("cp.async.cg.shared.global [%0], [%1], 16;"
                 :: "r"(dst), "l"(src));
}
__device__ __forceinline__ void mma_f16(float* d, const uint32_t* a,
                                        const uint32_t* b)
{
    asm volatile(
        "mma.sync.aligned.m16n8k16.row.col.f32.f16.f16.f32 "
        "{%0,%1,%2,%3}, {%4,%5,%6,%7}, {%8,%9}, {%0,%1,%2,%3};"
        : "+f"(d[0]), "+f"(d[1]), "+f"(d[2]), "+f"(d[3])
        : "r"(a[0]), "r"(a[1]), "r"(a[2]), "r"(a[3]), "r"(b[0]), "r"(b[1]));
}
__device__ __forceinline__ void ldsm4(uint32_t* r, uint32_t addr)
{
    asm volatile(
        "ldmatrix.sync.aligned.m8n8.x4.shared.b16 {%0,%1,%2,%3}, [%4];"
        : "=r"(r[0]), "=r"(r[1]), "=r"(r[2]), "=r"(r[3]) : "r"(addr));
}

// --------------------------- fp16 2-way split -------------------------------
__device__ __forceinline__ void h2split(float x, __half& h0, __half& h1)
{
    h0 = __float2half_rn(x);
    h1 = __float2half_rn(x - __half2float(h0));
}

// ===== shared MMA compute core (128x128 tile, 8 warps 2x4, one k32 step) ====
// A planes at sb+aBase (+p*8192), B planes at sb+bBase (+pb*8192).
// Swizzled rows: 32 fp16 (64B) per row, 16B chunk c -> c ^ ((r>>1)&3).
#define MMA_STEP(aBase, bBase)                                                 \
    do {                                                                       \
        _Pragma("unroll")                                                      \
        for (int h = 0; h < 2; h++) {                                          \
            uint32_t bfr[2][4][2];                                             \
            _Pragma("unroll")                                                  \
            for (int pb = 0; pb < 2; pb++)                                     \
                _Pragma("unroll")                                              \
                for (int jj = 0; jj < 2; jj++) {                               \
                    uint32_t r[4];                                             \
                    ldsm4(r, sb + (bBase) + pb * 8192 + bOff + jj * 1024 +     \
                             ((((uint32_t)(h * 2) + bCk) ^ bSwz) << 4));       \
                    bfr[pb][jj * 2][0] = r[0]; bfr[pb][jj * 2][1] = r[1];      \
                    bfr[pb][jj * 2 + 1][0] = r[2];                             \
                    bfr[pb][jj * 2 + 1][1] = r[3];                             \
                }                                                              \
            _Pragma("unroll")                                                  \
            for (int pa = 0; pa < 2; pa++) {                                   \
                uint32_t af[4][4];                                             \
                _Pragma("unroll")                                              \
                for (int i = 0; i < 4; i++)                                    \
                    ldsm4(af[i], sb + (aBase) + pa * 8192 + aOff + i * 1024 +  \
                                 ((((uint32_t)(h * 2) + aCk) ^ aSwz) << 4));   \
                const int npb = 2 - pa;                                        \
                for (int pb = 0; pb < npb; pb++)                               \
                    _Pragma("unroll")                                          \
                    for (int i = 0; i < 4; i++)                                \
                        _Pragma("unroll")                                      \
                        for (int j = 0; j < 4; j++)                            \
                            mma_f16(acc[i][j], af[i], bfr[pb][j]);             \
            }                                                                  \
        }                                                                      \
    } while (0)

#define MMA_EPILOGUE()                                                         \
    do {                                                                       \
        const int colBase = n0 + warp_n * 32 + (lane & 3) * 2;                 \
        const int rowBase = m0 + warp_m * 64 + (lane >> 2);                    \
        _Pragma("unroll")                                                      \
        for (int i = 0; i < 4; i++) {                                          \
            _Pragma("unroll")                                                  \
            for (int j = 0; j < 4; j++) {                                      \
                const int gc = colBase + j * 8;                                \
                float bx = 0.f, by = 0.f;                                      \
                if (bias) { bx = bias[gc]; by = bias[gc + 1]; }                \
                const int r0 = rowBase + i * 16;                               \
                if (r0 < M) {                                                  \
                    float2 v = make_float2(acc[i][j][0] * outScale + bx,       \
                                           acc[i][j][1] * outScale + by);      \
                    *(float2*)(C + (size_t)r0 * ldc + gc) = v;                 \
                }                                                              \
                const int r1 = r0 + 8;                                         \
                if (r1 < M) {                                                  \
                    float2 v = make_float2(acc[i][j][2] * outScale + bx,       \
                                           acc[i][j][3] * outScale + by);      \
                    *(float2*)(C + (size_t)r1 * ldc + gc) = v;                 \
                }                                                              \
            }                                                                  \
        }                                                                      \
    } while (0)

#define MMA_LDSM_COORDS()                                                      \
    const uint32_t aRow = (uint32_t)(warp_m * 64 + (lane & 15));               \
    const uint32_t aOff = aRow * 64;                                           \
    const uint32_t aSwz = (aRow >> 1) & 3;                                     \
    const uint32_t aCk = (uint32_t)(lane >> 4);                                \
    const uint32_t bRow =                                                      \
        (uint32_t)(warp_n * 32 + ((lane >> 4) << 3) + (lane & 7));             \
    const uint32_t bOff = bRow * 64;                                           \
    const uint32_t bSwz = (bRow >> 1) & 3;                                     \
    const uint32_t bCk = (uint32_t)((lane >> 3) & 1)

#define SMEM_TOT 65536

// ------------- fp16x2 HMMA GEMM, A already split (pw / out GEMMs) ----------
__global__ __launch_bounds__(256, 2) void mma_gemm(
    const __half* __restrict__ Ap, size_t aPlane, int lda,
    const __half* __restrict__ Bp, size_t bPlane, int ldb,
    float* __restrict__ C, int ldc, long long cSplitStride,
    int M, int kChunkTot, const float* __restrict__ bias, float outScale)
{
    extern __shared__ __align__(16) char smc[];
    const uint32_t sb = smem_u32(smc);
    const int tid = threadIdx.x, lane = tid & 31, wid = tid >> 5;
    const int warp_m = wid >> 2, warp_n = wid & 3;
    const int m0 = blockIdx.y * 128, n0 = blockIdx.x * 128;
    const int kBase = blockIdx.z * kChunkTot;
    C += (long long)blockIdx.z * cSplitStride;

    const int lr = tid >> 2, lc = tid & 3;
    const uint32_t swz = (uint32_t)(lc ^ ((lr >> 1) & 3)) << 4;
    const uint32_t d1 = (uint32_t)lr * 64 + swz;
    const uint32_t d2 = d1 + 64 * 64;
    const __half* aS = Ap + (size_t)(m0 + lr) * lda + kBase + lc * 8;
    const __half* bS = Bp + (size_t)(n0 + lr) * ldb + kBase + lc * 8;

#define ISSUE(bo, ke)                                                          \
    do {                                                                       \
        cp16(sb + (bo) + d1, aS + (ke));                                       \
        cp16(sb + (bo) + 8192 + d1, aS + aPlane + (ke));                       \
        cp16(sb + (bo) + d2, aS + (size_t)64 * lda + (ke));                    \
        cp16(sb + (bo) + 8192 + d2, aS + aPlane + (size_t)64 * lda + (ke));    \
        cp16(sb + (bo) + 16384 + d1, bS + (ke));                               \
        cp16(sb + (bo) + 24576 + d1, bS + bPlane + (ke));                      \
        cp16(sb + (bo) + 16384 + d2, bS + (size_t)64 * ldb + (ke));            \
        cp16(sb + (bo) + 24576 + d2, bS + bPlane + (size_t)64 * ldb + (ke));   \
        asm volatile("cp.async.commit_group;" ::: "memory");                   \
    } while (0)

    MMA_LDSM_COORDS();

    float acc[4][4][4];
#pragma unroll
    for (int i = 0; i < 4; i++)
#pragma unroll
        for (int j = 0; j < 4; j++)
#pragma unroll
            for (int e = 0; e < 4; e++) acc[i][j][e] = 0.f;

    const int nIter = kChunkTot / 32;
    ISSUE(0u, 0);
    uint32_t bo = 0;
    for (int it = 0; it < nIter; it++) {
        asm volatile("cp.async.wait_group 0;" ::: "memory");
        __syncthreads();
        if (it + 1 < nIter) ISSUE(bo ^ 32768u, (it + 1) * 32);
        MMA_STEP(bo, bo + 16384);
        bo ^= 32768u;
    }
#undef ISSUE

    MMA_EPILOGUE();
}

// ------- fp16x2 HMMA GEMM, A fp32 with in-kernel split (value GEMM) --------
// A: fp32 row-major (lda). LDG-pipelined, split at STS time into 2 planes.
// Layout: A planes double-buffered at 0/16384; B 2-stage at 32768/49152.
__global__ __launch_bounds__(256, 2) void mma_gemm_f32(
    const float* __restrict__ A, int lda,
    const __half* __restrict__ Bp, size_t bPlane, int ldb,
    float* __restrict__ C, int ldc,
    int M, int kChunkTot, const float* __restrict__ bias, float outScale)
{
    extern __shared__ __align__(16) char smc[];
    const uint32_t sb = smem_u32(smc);
    const int tid = threadIdx.x, lane = tid & 31, wid = tid >> 5;
    const int warp_m = wid >> 2, warp_n = wid & 3;
    const int m0 = blockIdx.y * 128, n0 = blockIdx.x * 128;

    // ---- A LDG coords: thread -> row tid/2, k-half (tid&1)*16 ----
    const int row = tid >> 1;
    const int kh = (tid & 1) * 16;
    const bool aval = (m0 + row) < M;
    const float* aRowP = A + (size_t)(m0 + row) * lda + kh;
    // STS chunks for this thread: c0 = (tid&1)*2, c0+1
    const uint32_t sw = ((uint32_t)row >> 1) & 3;
    const uint32_t c0 = (uint32_t)(tid & 1) * 2;
    const uint32_t aoff0 = (uint32_t)row * 64 + ((c0 ^ sw) << 4);
    const uint32_t aoff1 = (uint32_t)row * 64 + (((c0 + 1) ^ sw) << 4);

    // ---- B cp.async coords ----
    const int lr = tid >> 2, lc = tid & 3;
    const uint32_t swz = (uint32_t)(lc ^ ((lr >> 1) & 3)) << 4;
    const uint32_t d1 = (uint32_t)lr * 64 + swz;
    const uint32_t d2 = d1 + 64 * 64;
    const __half* bS = Bp + (size_t)(n0 + lr) * ldb + lc * 8;

#define ISSUEB(bo, ke)                                                         \
    do {                                                                       \
        cp16(sb + (bo) + d1, bS + (ke));                                       \
        cp16(sb + (bo) + 8192 + d1, bS + bPlane + (ke));                       \
        cp16(sb + (bo) + d2, bS + (size_t)64 * ldb + (ke));                    \
        cp16(sb + (bo) + 8192 + d2, bS + bPlane + (size_t)64 * ldb + (ke));    \
        asm volatile("cp.async.commit_group;" ::: "memory");                   \
    } while (0)

    MMA_LDSM_COORDS();

    float acc[4][4][4];
#pragma unroll
    for (int i = 0; i < 4; i++)
#pragma unroll
        for (int j = 0; j < 4; j++)
#pragma unroll
            for (int e = 0; e < 4; e++) acc[i][j][e] = 0.f;

    const int nIter = kChunkTot / 32;

    // prologue: A regs for iter 0, B stage 0
    float fa[16];
#pragma unroll
    for (int j = 0; j < 4; j++) {
        float4 v = aval ? *(const float4*)(aRowP + j * 4)
                        : make_float4(0.f, 0.f, 0.f, 0.f);
        fa[j * 4 + 0] = v.x; fa[j * 4 + 1] = v.y;
        fa[j * 4 + 2] = v.z; fa[j * 4 + 3] = v.w;
    }
    ISSUEB(32768u, 0);

    for (int it = 0; it < nIter; it++) {
        // split + STS into A buffer it&1
        {
            const uint32_t aBase = (uint32_t)(it & 1) * 16384u;
            unsigned short h0[16], h1[16];
#pragma unroll
            for (int e = 0; e < 16; e++) {
                __half a0, a1;
                h2split(fa[e], a0, a1);
                h0[e] = __half_as_ushort(a0);
                h1[e] = __half_as_ushort(a1);
            }
            uint4 q;
            q.x = (uint32_t)h0[0] | ((uint32_t)h0[1] << 16);
            q.y = (uint32_t)h0[2] | ((uint32_t)h0[3] << 16);
            q.z = (uint32_t)h0[4] | ((uint32_t)h0[5] << 16);
            q.w = (uint32_t)h0[6] | ((uint32_t)h0[7] << 16);
            *(uint4*)(smc + aBase + aoff0) = q;
            q.x = (uint32_t)h0[8] | ((uint32_t)h0[9] << 16);
            q.y = (uint32_t)h0[10] | ((uint32_t)h0[11] << 16);
            q.z = (uint32_t)h0[12] | ((uint32_t)h0[13] << 16);
            q.w = (uint32_t)h0[14] | ((uint32_t)h0[15] << 16);
            *(uint4*)(smc + aBase + aoff1) = q;
            q.x = (uint32_t)h1[0] | ((uint32_t)h1[1] << 16);
            q.y = (uint32_t)h1[2] | ((uint32_t)h1[3] << 16);
            q.z = (uint32_t)h1[4] | ((uint32_t)h1[5] << 16);
            q.w = (uint32_t)h1[6] | ((uint32_t)h1[7] << 16);
            *(uint4*)(smc + aBase + 8192 + aoff0) = q;
            q.x = (uint32_t)h1[8] | ((uint32_t)h1[9] << 16);
            q.y = (uint32_t)h1[10] | ((uint32_t)h1[11] << 16);
            q.z = (uint32_t)h1[12] | ((uint32_t)h1[13] << 16);
            q.w = (uint32_t)h1[14] | ((uint32_t)h1[15] << 16);
            *(uint4*)(smc + aBase + 8192 + aoff1) = q;
        }
        // prefetch A regs for next iter
        if (it + 1 < nIter) {
#pragma unroll
            for (int j = 0; j < 4; j++) {
                float4 v = aval
                    ? *(const float4*)(aRowP + (it + 1) * 32 + j * 4)
                    : make_float4(0.f, 0.f, 0.f, 0.f);
                fa[j * 4 + 0] = v.x; fa[j * 4 + 1] = v.y;
                fa[j * 4 + 2] = v.z; fa[j * 4 + 3] = v.w;
            }
        }
        asm volatile("cp.async.wait_group 0;" ::: "memory");
        __syncthreads();
        if (it + 1 < nIter)
            ISSUEB(32768u + (uint32_t)((it + 1) & 1) * 16384u, (it + 1) * 32);

        const uint32_t aBase = (uint32_t)(it & 1) * 16384u;
        const uint32_t bBase = 32768u + (uint32_t)(it & 1) * 16384u;
        MMA_STEP(aBase, bBase);
    }
#undef ISSUEB

    MMA_EPILOGUE();
}

// -------------- weight transpose + scale(x64) + fp16 2-way split ------------
// W is [K][N] fp32; out planes are [Ntot][K] fp16, rows offset by rowOff.
__global__ __launch_bounds__(256) void k_tsplit(
    const float* __restrict__ W, int K, int N,
    __half* __restrict__ out, size_t plane, int rowOff)
{
    __shared__ float t[32][33];
    const int kb = blockIdx.y * 32, nb = blockIdx.x * 32;
    const int c = threadIdx.x & 31, r8 = threadIdx.x >> 5;
#pragma unroll
    for (int i = 0; i < 4; i++)
        t[r8 + i * 8][c] = W[(size_t)(kb + r8 + i * 8) * N + nb + c];
    __syncthreads();
#pragma unroll
    for (int i = 0; i < 4; i++) {
        const int n = nb + r8 + i * 8;
        const int k = kb + c;
        float x = t[c][r8 + i * 8] * WSCALE;
        __half h0, h1;
        h2split(x, h0, h1);
        size_t o = (size_t)(n + rowOff) * K + k;
        out[o] = h0;
        out[plane + o] = h1;
    }
}

// Batched variant for the two 256x256 weights (Wv, Wo) in one launch.
__global__ __launch_bounds__(256) void k_tsplit2(
    const float* __restrict__ W0, __half* __restrict__ o0,
    const float* __restrict__ W1, __half* __restrict__ o1)
{
    __shared__ float t[32][33];
    const float* W = blockIdx.z ? W1 : W0;
    __half* out = blockIdx.z ? o1 : o0;
    const size_t plane = (size_t)CDIM * CDIM;
    const int kb = blockIdx.y * 32, nb = blockIdx.x * 32;
    const int c = threadIdx.x & 31, r8 = threadIdx.x >> 5;
#pragma unroll
    for (int i = 0; i < 4; i++)
        t[r8 + i * 8][c] = W[(size_t)(kb + r8 + i * 8) * CDIM + nb + c];
    __syncthreads();
#pragma unroll
    for (int i = 0; i < 4; i++) {
        const int n = nb + r8 + i * 8;
        const int k = kb + c;
        float x = t[c][r8 + i * 8] * WSCALE;
        __half h0, h1;
        h2split(x, h0, h1);
        size_t o = (size_t)n * CDIM + k;
        out[o] = h0;
        out[plane + o] = h1;
    }
}

// --------------------------- bilinear helper -------------------------------
__device__ __forceinline__ float bilin(const float* __restrict__ base,
                                       int Hl, int Wl, int stride,
                                       float y, float x)
{
    float fy = floorf(y), fx = floorf(x);
    int y0 = (int)fy, x0 = (int)fx;
    float wy1 = y - fy, wx1 = x - fx;
    float wy0 = 1.f - wy1, wx0 = 1.f - wx1;
    float v = 0.f;
    bool xa = (x0 >= 0) && (x0 < Wl);
    bool xb = (x0 + 1 >= 0) && (x0 + 1 < Wl);
    if (y0 >= 0 && y0 < Hl) {
        if (xa) v += base[(y0 * Wl + x0) * stride] * (wy0 * wx0);
        if (xb) v += base[(y0 * Wl + x0 + 1) * stride] * (wy0 * wx1);
    }
    if (y0 + 1 >= 0 && y0 + 1 < Hl) {
        if (xa) v += base[((y0 + 1) * Wl + x0) * stride] * (wy1 * wx0);
        if (xb) v += base[((y0 + 1) * Wl + x0 + 1) * stride] * (wy1 * wx1);
    }
    return v;
}

// ------------------- ROI align -> split fp16 planes -------------------------
__global__ __launch_bounds__(256) void k_roi(const float* __restrict__ ref,
                                             const float* __restrict__ value,
                                             __half* __restrict__ roiA)
{
    int q = blockIdx.x;
    int n = q / LQ;
    int t = threadIdx.x;
    __shared__ float sr[4];
    if (t < 4) sr[t] = ref[(size_t)q * 16 + t];
    __syncthreads();
    const float cx = sr[0], cy = sr[1], w = sr[2], h = sr[3];
    const float x1 = (cx - 0.5f * w) * 150.f - 0.5f;
    const float y1 = (cy - 0.5f * h) * 100.f - 0.5f;
    const float bw = w * 150.f / (float)ROI;
    const float bh = h * 100.f / (float)ROI;
    const float* base = value + (size_t)n * LEN_IN * CDIM + t;
    __half* out0 = roiA + (size_t)q * ROI_DIM;
    __half* out1 = out0 + (size_t)NQPAD * ROI_DIM;
    for (int by = 0; by < ROI; by++) {
        float y = y1 + bh * ((float)by + 0.5f);
        for (int bx = 0; bx < ROI; bx++) {
            float x = x1 + bw * ((float)bx + 0.5f);
            float v = bilin(base, 100, 150, CDIM, y, x);
            __half h0, h1;
            h2split(v, h0, h1);
            out0[(by * ROI + bx) * CDIM + t] = h0;
            out1[(by * ROI + bx) * CDIM + t] = h1;
        }
    }
}

// ------------------------- split-K reduce + bias ----------------------------
__global__ __launch_bounds__(256) void k_reduce(const float* __restrict__ part,
                                                const float* __restrict__ bp,
                                                const float* __restrict__ bw,
                                                float* __restrict__ pw)
{
    int i = blockIdx.x * 256 + threadIdx.x;
    if (i >= NQ * NPW) return;
    int j = i % NPW;
    float s = (j < 256) ? bp[j] : bw[j - 256];
#pragma unroll
    for (int z = 0; z < SPLITK; z++) s += part[(size_t)z * NQ * NPW + i];
    pw[i] = s;
}

// -------- deformable sampling + weighted sum -> split fp16 att planes -------
__global__ __launch_bounds__(256) void k_sample(const float* __restrict__ ref,
                                                const float* __restrict__ pw,
                                                const float* __restrict__ value,
                                                __half* __restrict__ attA)
{
    int q = blockIdx.x;
    int n = q / LQ;
    int t = threadIdx.x;
    int h = t >> 5, d = t & 31;
    __shared__ float s_px[NHEADS][16];
    __shared__ float s_py[NHEADS][16];
    __shared__ float s_w[NHEADS][16];
    __shared__ float s_ref[16];
    if (t < 16) s_ref[t] = ref[(size_t)q * 16 + t];
    __syncthreads();
    const float* row = pw + (size_t)q * NPW;
    if (t < 128) {
        int hh = t >> 4, lp = t & 15, l = lp >> 2;
        float ox = tanhf(row[2 * t]);
        float oy = tanhf(row[2 * t + 1]);
        s_px[hh][lp] = s_ref[l * 4 + 0] + ox * s_ref[l * 4 + 2] * 0.5f;
        s_py[hh][lp] = s_ref[l * 4 + 1] + oy * s_ref[l * 4 + 3] * 0.5f;
        s_w[hh][lp] = row[256 + t];
    }
    __syncthreads();
    if (t < NHEADS) {
        float mx = -1e30f;
#pragma unroll
        for (int i = 0; i < 16; i++) mx = fmaxf(mx, s_w[t][i]);
        float sum = 0.f;
#pragma unroll
        for (int i = 0; i < 16; i++) {
            float e = expf(s_w[t][i] - mx);
            s_w[t][i] = e;
            sum += e;
        }
        float inv = 1.f / sum;
#pragma unroll
        for (int i = 0; i < 16; i++) s_w[t][i] *= inv;
    }
    __syncthreads();
    const int HL[4] = {100, 50, 25, 13};
    const int WL[4] = {150, 75, 38, 19};
    const int SL[4] = {0, 15000, 18750, 19700};
    float acc = 0.f;
#pragma unroll
    for (int l = 0; l < NLVL; l++) {
        const float* base =
            value + ((size_t)n * LEN_IN + SL[l]) * CDIM + h * DH + d;
#pragma unroll
        for (int p = 0; p < NPTS; p++) {
            int lp = l * 4 + p;
            float px = s_px[h][lp] * (float)WL[l] - 0.5f;
            float py = s_py[h][lp] * (float)HL[l] - 0.5f;
            acc += s_w[h][lp] * bilin(base, HL[l], WL[l], CDIM, py, px);
        }
    }
    __half h0, h1;
    h2split(acc, h0, h1);
    attA[(size_t)q * CDIM + t] = h0;
    attA[(size_t)NQPAD * CDIM + (size_t)q * CDIM + t] = h1;
}

// ------------------------------ launcher -----------------------------------
extern "C" void kernel_launch(void* const* d_in, const int* in_sizes, int n_in,
                              void* d_out, int out_size)
{
    (void)in_sizes; (void)n_in; (void)out_size;
    const float* ref  = (const float*)d_in[1];
    const float* flat = (const float*)d_in[2];
    const float* Wv   = (const float*)d_in[6];
    const float* bv   = (const float*)d_in[7];
    const float* Wp   = (const float*)d_in[8];
    const float* bp   = (const float*)d_in[9];
    const float* Ww   = (const float*)d_in[10];
    const float* bw   = (const float*)d_in[11];
    const float* Wo   = (const float*)d_in[12];
    const float* bo   = (const float*)d_in[13];
    float* out = (float*)d_out;

    float *p_value, *p_part, *p_pw;
    __half *p_roiA, *p_attA, *p_btv, *p_btpw, *p_btwo;
    cudaGetSymbolAddress((void**)&p_value, g_value);
    cudaGetSymbolAddress((void**)&p_roiA,  g_roiA);
    cudaGetSymbolAddress((void**)&p_attA,  g_attA);
    cudaGetSymbolAddress((void**)&p_part,  g_part);
    cudaGetSymbolAddress((void**)&p_pw,    g_pw);
    cudaGetSymbolAddress((void**)&p_btv,   g_btv);
    cudaGetSymbolAddress((void**)&p_btpw,  g_btpw);
    cudaGetSymbolAddress((void**)&p_btwo,  g_btwo);

    cudaFuncSetAttribute(mma_gemm, cudaFuncAttributeMaxDynamicSharedMemorySize,
                         SMEM_TOT);
    cudaFuncSetAttribute(mma_gemm_f32,
                         cudaFuncAttributeMaxDynamicSharedMemorySize, SMEM_TOT);

    // 0. weight transpose + x64 scale + fp16 split
    k_tsplit2<<<dim3(CDIM / 32, CDIM / 32, 2), 256>>>(Wv, p_btv, Wo, p_btwo);
    k_tsplit<<<dim3(256 / 32, ROI_DIM / 32), 256>>>(
        Wp, ROI_DIM, 256, p_btpw, (size_t)NPW * ROI_DIM, 0);
    k_tsplit<<<dim3(128 / 32, ROI_DIM / 32), 256>>>(
        Ww, ROI_DIM, 128, p_btpw, (size_t)NPW * ROI_DIM, 256);

    // 1. value = input_flatten @ Wv + bv  (A split fused; grid 2 x 624)
    mma_gemm_f32<<<dim3(CDIM / 128, (MV + 127) / 128, 1), 256, SMEM_TOT>>>(
        flat, CDIM,
        p_btv, (size_t)CDIM * CDIM, CDIM,
        p_value, CDIM, MV, CDIM, bv, WSCALE_INV);

    // 2. ROI align -> split fp16 roi planes
    k_roi<<<NQ, 256>>>(ref, p_value, p_roiA);

    // 3. pw partials: roi @ [Wp | Ww]  (grid 3 x 10 x 28)
    mma_gemm<<<dim3(NPW / 128, NQPAD / 128, SPLITK), 256, SMEM_TOT>>>(
        p_roiA, (size_t)NQPAD * ROI_DIM, ROI_DIM,
        p_btpw, (size_t)NPW * ROI_DIM, ROI_DIM,
        p_part, NPW, (long long)NQ * NPW, NQ, KCHUNK, nullptr, WSCALE_INV);
    k_reduce<<<(NQ * NPW + 255) / 256, 256>>>(p_part, bp, bw, p_pw);

    // 4. deformable sampling -> split fp16 att planes
    k_sample<<<NQ, 256>>>(ref, p_pw, p_value, p_attA);

    // 5. out = att @ Wo + bo  (grid 2 x 10)
    mma_gemm<<<dim3(CDIM / 128, NQPAD / 128, 1), 256, SMEM_TOT>>>(
        p_attA, (size_t)NQPAD * CDIM, CDIM,
        p_btwo, (size_t)CDIM * CDIM, CDIM,
        out, CDIM, 0, NQ, CDIM, bo, WSCALE_INV);
}

// round 10
// speedup vs baseline: 1.0420x; 1.0208x over previous
#include <cuda_runtime.h>
#include <cuda_fp16.h>
#include <math.h>
#include <cstdint>

// ---------------------------------------------------------------------------
// MSMDDeformRegionAttn  (N=4, Lq=300, C=256, H=8, Dh=32, L=4, P=4, ROI=7)
//
//   1. value = input_flatten @ Wv + bv            (79788 x 256 x 256)  HMMA
//      (A-operand fp32 -> fp16x2 split fused into the GEMM A-load)
//   2. ROI-align 7x7 on level-0 feature map -> roi planes (fp16 split)
//   3. pw partials = roi_flat @ [Wp | Ww]         (1200 x 12544 x 384) HMMA
//   4. k_sample: split-K reduce + bias (fused) + tanh offsets + softmax
//      + deformable bilinear gather -> att planes
//   5. out = att @ Wo + bo                        (1200 x 256 x 256)   HMMA
//
// All GEMMs: mma.sync m16n8k16 fp16 with 2-way fp16 split of each fp32
// operand and 3 cross-products (00, 01, 10) -> residual ~2^-22. Weights
// pre-scaled x64 (epilogue x 1/64) to keep residuals in fp16 normal range.
// ---------------------------------------------------------------------------

#define NBATCH  4
#define LQ      300
#define NQ      (NBATCH * LQ)      // 1200
#define CDIM    256
#define NHEADS  8
#define DH      32
#define NLVL    4
#define NPTS    4
#define ROI     7
#define LEN_IN  19947
#define ROI_DIM (ROI * ROI * CDIM) // 12544
#define NPW     384                // 256 (Wp) + 128 (Ww)
#define SPLITK  28
#define KCHUNK  (ROI_DIM / SPLITK) // 448 = 14 * 32
#define MV      (NBATCH * LEN_IN)  // 79788
#define NQPAD   1280               // 10 * 128
#define WSCALE  64.0f
#define WSCALE_INV (1.0f / 64.0f)

// ------------------------- scratch (static device mem) ---------------------
__device__ float  g_value[(size_t)MV * CDIM];                  // 81.7 MB
__device__ __half g_roiA[(size_t)2 * NQPAD * ROI_DIM];         // 64.2 MB
__device__ __half g_attA[(size_t)2 * NQPAD * CDIM];            //  1.3 MB
__device__ float  g_part[(size_t)SPLITK * NQ * NPW];           // 51.6 MB
__device__ __half g_btv[(size_t)2 * CDIM * CDIM];
__device__ __half g_btpw[(size_t)2 * NPW * ROI_DIM];           // 19.3 MB
__device__ __half g_btwo[(size_t)2 * CDIM * CDIM];

// --------------------------- PTX primitives --------------------------------
__device__ __forceinline__ uint32_t smem_u32(const void* p)
{
    uint32_t a;
    asm("{ .reg .u64 t; cvta.to.shared.u64 t, %1; cvt.u32.u64 %0, t; }"
        : "=r"(a) : "l"(p));
    return a;
}
__device__ __forceinline__ void cp16(uint32_t dst, const void* src)
{
    asm volatile("cp.async.cg.shared.global [%0], [%1], 16;"
                 :: "r"(dst), "l"(src));
}
__device__ __forceinline__ void mma_f16(float* d, const uint32_t* a,
                                        const uint32_t* b)
{
    asm volatile(
        "mma.sync.aligned.m16n8k16.row.col.f32.f16.f16.f32 "
        "{%0,%1,%2,%3}, {%4,%5,%6,%7}, {%8,%9}, {%0,%1,%2,%3};"
        : "+f"(d[0]), "+f"(d[1]), "+f"(d[2]), "+f"(d[3])
        : "r"(a[0]), "r"(a[1]), "r"(a[2]), "r"(a[3]), "r"(b[0]), "r"(b[1]));
}
__device__ __forceinline__ void ldsm4(uint32_t* r, uint32_t addr)
{
    asm volatile(
        "ldmatrix.sync.aligned.m8n8.x4.shared.b16 {%0,%1,%2,%3}, [%4];"
        : "=r"(r[0]), "=r"(r[1]), "=r"(r[2]), "=r"(r[3]) : "r"(addr));
}

// --------------------------- fp16 2-way split -------------------------------
__device__ __forceinline__ void h2split(float x, __half& h0, __half& h1)
{
    h0 = __float2half_rn(x);
    h1 = __float2half_rn(x - __half2float(h0));
}

// ===== shared MMA compute core (128x128 tile, 8 warps 2x4, one k32 step) ====
#define MMA_STEP(aBase, bBase)                                                 \
    do {                                                                       \
        _Pragma("unroll")                                                      \
        for (int h = 0; h < 2; h++) {                                          \
            uint32_t bfr[2][4][2];                                             \
            _Pragma("unroll")                                                  \
            for (int pb = 0; pb < 2; pb++)                                     \
                _Pragma("unroll")                                              \
                for (int jj = 0; jj < 2; jj++) {                               \
                    uint32_t r[4];                                             \
                    ldsm4(r, sb + (bBase) + pb * 8192 + bOff + jj * 1024 +     \
                             ((((uint32_t)(h * 2) + bCk) ^ bSwz) << 4));       \
                    bfr[pb][jj * 2][0] = r[0]; bfr[pb][jj * 2][1] = r[1];      \
                    bfr[pb][jj * 2 + 1][0] = r[2];                             \
                    bfr[pb][jj * 2 + 1][1] = r[3];                             \
                }                                                              \
            _Pragma("unroll")                                                  \
            for (int pa = 0; pa < 2; pa++) {                                   \
                uint32_t af[4][4];                                             \
                _Pragma("unroll")                                              \
                for (int i = 0; i < 4; i++)                                    \
                    ldsm4(af[i], sb + (aBase) + pa * 8192 + aOff + i * 1024 +  \
                                 ((((uint32_t)(h * 2) + aCk) ^ aSwz) << 4));   \
                const int npb = 2 - pa;                                        \
                for (int pb = 0; pb < npb; pb++)                               \
                    _Pragma("unroll")                                          \
                    for (int i = 0; i < 4; i++)                                \
                        _Pragma("unroll")                                      \
                        for (int j = 0; j < 4; j++)                            \
                            mma_f16(acc[i][j], af[i], bfr[pb][j]);             \
            }                                                                  \
        }                                                                      \
    } while (0)

#define MMA_EPILOGUE()                                                         \
    do {                                                                       \
        const int colBase = n0 + warp_n * 32 + (lane & 3) * 2;                 \
        const int rowBase = m0 + warp_m * 64 + (lane >> 2);                    \
        _Pragma("unroll")                                                      \
        for (int i = 0; i < 4; i++) {                                          \
            _Pragma("unroll")                                                  \
            for (int j = 0; j < 4; j++) {                                      \
                const int gc = colBase + j * 8;                                \
                float bx = 0.f, by = 0.f;                                      \
                if (bias) { bx = bias[gc]; by = bias[gc + 1]; }                \
                const int r0 = rowBase + i * 16;                               \
                if (r0 < M) {                                                  \
                    float2 v = make_float2(acc[i][j][0] * outScale + bx,       \
                                           acc[i][j][1] * outScale + by);      \
                    *(float2*)(C + (size_t)r0 * ldc + gc) = v;                 \
                }                                                              \
                const int r1 = r0 + 8;                                         \
                if (r1 < M) {                                                  \
                    float2 v = make_float2(acc[i][j][2] * outScale + bx,       \
                                           acc[i][j][3] * outScale + by);      \
                    *(float2*)(C + (size_t)r1 * ldc + gc) = v;                 \
                }                                                              \
            }                                                                  \
        }                                                                      \
    } while (0)

#define MMA_LDSM_COORDS()                                                      \
    const uint32_t aRow = (uint32_t)(warp_m * 64 + (lane & 15));               \
    const uint32_t aOff = aRow * 64;                                           \
    const uint32_t aSwz = (aRow >> 1) & 3;                                     \
    const uint32_t aCk = (uint32_t)(lane >> 4);                                \
    const uint32_t bRow =                                                      \
        (uint32_t)(warp_n * 32 + ((lane >> 4) << 3) + (lane & 7));             \
    const uint32_t bOff = bRow * 64;                                           \
    const uint32_t bSwz = (bRow >> 1) & 3;                                     \
    const uint32_t bCk = (uint32_t)((lane >> 3) & 1)

#define SMEM_TOT 65536

// ------------- fp16x2 HMMA GEMM, A already split (pw / out GEMMs) ----------
__global__ __launch_bounds__(256, 2) void mma_gemm(
    const __half* __restrict__ Ap, size_t aPlane, int lda,
    const __half* __restrict__ Bp, size_t bPlane, int ldb,
    float* __restrict__ C, int ldc, long long cSplitStride,
    int M, int kChunkTot, const float* __restrict__ bias, float outScale)
{
    extern __shared__ __align__(16) char smc[];
    const uint32_t sb = smem_u32(smc);
    const int tid = threadIdx.x, lane = tid & 31, wid = tid >> 5;
    const int warp_m = wid >> 2, warp_n = wid & 3;
    const int m0 = blockIdx.y * 128, n0 = blockIdx.x * 128;
    const int kBase = blockIdx.z * kChunkTot;
    C += (long long)blockIdx.z * cSplitStride;

    const int lr = tid >> 2, lc = tid & 3;
    const uint32_t swz = (uint32_t)(lc ^ ((lr >> 1) & 3)) << 4;
    const uint32_t d1 = (uint32_t)lr * 64 + swz;
    const uint32_t d2 = d1 + 64 * 64;
    const __half* aS = Ap + (size_t)(m0 + lr) * lda + kBase + lc * 8;
    const __half* bS = Bp + (size_t)(n0 + lr) * ldb + kBase + lc * 8;

#define ISSUE(bo, ke)                                                          \
    do {                                                                       \
        cp16(sb + (bo) + d1, aS + (ke));                                       \
        cp16(sb + (bo) + 8192 + d1, aS + aPlane + (ke));                       \
        cp16(sb + (bo) + d2, aS + (size_t)64 * lda + (ke));                    \
        cp16(sb + (bo) + 8192 + d2, aS + aPlane + (size_t)64 * lda + (ke));    \
        cp16(sb + (bo) + 16384 + d1, bS + (ke));                               \
        cp16(sb + (bo) + 24576 + d1, bS + bPlane + (ke));                      \
        cp16(sb + (bo) + 16384 + d2, bS + (size_t)64 * ldb + (ke));            \
        cp16(sb + (bo) + 24576 + d2, bS + bPlane + (size_t)64 * ldb + (ke));   \
        asm volatile("cp.async.commit_group;" ::: "memory");                   \
    } while (0)

    MMA_LDSM_COORDS();

    float acc[4][4][4];
#pragma unroll
    for (int i = 0; i < 4; i++)
#pragma unroll
        for (int j = 0; j < 4; j++)
#pragma unroll
            for (int e = 0; e < 4; e++) acc[i][j][e] = 0.f;

    const int nIter = kChunkTot / 32;
    ISSUE(0u, 0);
    uint32_t bo = 0;
    for (int it = 0; it < nIter; it++) {
        asm volatile("cp.async.wait_group 0;" ::: "memory");
        __syncthreads();
        if (it + 1 < nIter) ISSUE(bo ^ 32768u, (it + 1) * 32);
        MMA_STEP(bo, bo + 16384);
        bo ^= 32768u;
    }
#undef ISSUE

    MMA_EPILOGUE();
}

// ------- fp16x2 HMMA GEMM, A fp32 with in-kernel split (value GEMM) --------
__global__ __launch_bounds__(256, 2) void mma_gemm_f32(
    const float* __restrict__ A, int lda,
    const __half* __restrict__ Bp, size_t bPlane, int ldb,
    float* __restrict__ C, int ldc,
    int M, int kChunkTot, const float* __restrict__ bias, float outScale)
{
    extern __shared__ __align__(16) char smc[];
    const uint32_t sb = smem_u32(smc);
    const int tid = threadIdx.x, lane = tid & 31, wid = tid >> 5;
    const int warp_m = wid >> 2, warp_n = wid & 3;
    const int m0 = blockIdx.y * 128, n0 = blockIdx.x * 128;

    const int row = tid >> 1;
    const int kh = (tid & 1) * 16;
    const bool aval = (m0 + row) < M;
    const float* aRowP = A + (size_t)(m0 + row) * lda + kh;
    const uint32_t sw = ((uint32_t)row >> 1) & 3;
    const uint32_t c0 = (uint32_t)(tid & 1) * 2;
    const uint32_t aoff0 = (uint32_t)row * 64 + ((c0 ^ sw) << 4);
    const uint32_t aoff1 = (uint32_t)row * 64 + (((c0 + 1) ^ sw) << 4);

    const int lr = tid >> 2, lc = tid & 3;
    const uint32_t swz = (uint32_t)(lc ^ ((lr >> 1) & 3)) << 4;
    const uint32_t d1 = (uint32_t)lr * 64 + swz;
    const uint32_t d2 = d1 + 64 * 64;
    const __half* bS = Bp + (size_t)(n0 + lr) * ldb + lc * 8;

#define ISSUEB(bo, ke)                                                         \
    do {                                                                       \
        cp16(sb + (bo) + d1, bS + (ke));                                       \
        cp16(sb + (bo) + 8192 + d1, bS + bPlane + (ke));                       \
        cp16(sb + (bo) + d2, bS + (size_t)64 * ldb + (ke));                    \
        cp16(sb + (bo) + 8192 + d2, bS + bPlane + (size_t)64 * ldb + (ke));    \
        asm volatile("cp.async.commit_group;" ::: "memory");                   \
    } while (0)

    MMA_LDSM_COORDS();

    float acc[4][4][4];
#pragma unroll
    for (int i = 0; i < 4; i++)
#pragma unroll
        for (int j = 0; j < 4; j++)
#pragma unroll
            for (int e = 0; e < 4; e++) acc[i][j][e] = 0.f;

    const int nIter = kChunkTot / 32;

    float fa[16];
#pragma unroll
    for (int j = 0; j < 4; j++) {
        float4 v = aval ? *(const float4*)(aRowP + j * 4)
                        : make_float4(0.f, 0.f, 0.f, 0.f);
        fa[j * 4 + 0] = v.x; fa[j * 4 + 1] = v.y;
        fa[j * 4 + 2] = v.z; fa[j * 4 + 3] = v.w;
    }
    ISSUEB(32768u, 0);

    for (int it = 0; it < nIter; it++) {
        {
            const uint32_t aBase = (uint32_t)(it & 1) * 16384u;
            unsigned short h0[16], h1[16];
#pragma unroll
            for (int e = 0; e < 16; e++) {
                __half a0, a1;
                h2split(fa[e], a0, a1);
                h0[e] = __half_as_ushort(a0);
                h1[e] = __half_as_ushort(a1);
            }
            uint4 q;
            q.x = (uint32_t)h0[0] | ((uint32_t)h0[1] << 16);
            q.y = (uint32_t)h0[2] | ((uint32_t)h0[3] << 16);
            q.z = (uint32_t)h0[4] | ((uint32_t)h0[5] << 16);
            q.w = (uint32_t)h0[6] | ((uint32_t)h0[7] << 16);
            *(uint4*)(smc + aBase + aoff0) = q;
            q.x = (uint32_t)h0[8] | ((uint32_t)h0[9] << 16);
            q.y = (uint32_t)h0[10] | ((uint32_t)h0[11] << 16);
            q.z = (uint32_t)h0[12] | ((uint32_t)h0[13] << 16);
            q.w = (uint32_t)h0[14] | ((uint32_t)h0[15] << 16);
            *(uint4*)(smc + aBase + aoff1) = q;
            q.x = (uint32_t)h1[0] | ((uint32_t)h1[1] << 16);
            q.y = (uint32_t)h1[2] | ((uint32_t)h1[3] << 16);
            q.z = (uint32_t)h1[4] | ((uint32_t)h1[5] << 16);
            q.w = (uint32_t)h1[6] | ((uint32_t)h1[7] << 16);
            *(uint4*)(smc + aBase + 8192 + aoff0) = q;
            q.x = (uint32_t)h1[8] | ((uint32_t)h1[9] << 16);
            q.y = (uint32_t)h1[10] | ((uint32_t)h1[11] << 16);
            q.z = (uint32_t)h1[12] | ((uint32_t)h1[13] << 16);
            q.w = (uint32_t)h1[14] | ((uint32_t)h1[15] << 16);
            *(uint4*)(smc + aBase + 8192 + aoff1) = q;
        }
        if (it + 1 < nIter) {
#pragma unroll
            for (int j = 0; j < 4; j++) {
                float4 v = aval
                    ? *(const float4*)(aRowP + (it + 1) * 32 + j * 4)
                    : make_float4(0.f, 0.f, 0.f, 0.f);
                fa[j * 4 + 0] = v.x; fa[j * 4 + 1] = v.y;
                fa[j * 4 + 2] = v.z; fa[j * 4 + 3] = v.w;
            }
        }
        asm volatile("cp.async.wait_group 0;" ::: "memory");
        __syncthreads();
        if (it + 1 < nIter)
            ISSUEB(32768u + (uint32_t)((it + 1) & 1) * 16384u, (it + 1) * 32);

        const uint32_t aBase = (uint32_t)(it & 1) * 16384u;
        const uint32_t bBase = 32768u + (uint32_t)(it & 1) * 16384u;
        MMA_STEP(aBase, bBase);
    }
#undef ISSUEB

    MMA_EPILOGUE();
}

// -------------- weight transpose + scale(x64) + fp16 2-way split ------------
// Batched for the two 256x256 weights (Wv, Wo) in one launch.
__global__ __launch_bounds__(256) void k_tsplit2(
    const float* __restrict__ W0, __half* __restrict__ o0,
    const float* __restrict__ W1, __half* __restrict__ o1)
{
    __shared__ float t[32][33];
    const float* W = blockIdx.z ? W1 : W0;
    __half* out = blockIdx.z ? o1 : o0;
    const size_t plane = (size_t)CDIM * CDIM;
    const int kb = blockIdx.y * 32, nb = blockIdx.x * 32;
    const int c = threadIdx.x & 31, r8 = threadIdx.x >> 5;
#pragma unroll
    for (int i = 0; i < 4; i++)
        t[r8 + i * 8][c] = W[(size_t)(kb + r8 + i * 8) * CDIM + nb + c];
    __syncthreads();
#pragma unroll
    for (int i = 0; i < 4; i++) {
        const int n = nb + r8 + i * 8;
        const int k = kb + c;
        float x = t[c][r8 + i * 8] * WSCALE;
        __half h0, h1;
        h2split(x, h0, h1);
        size_t o = (size_t)n * CDIM + k;
        out[o] = h0;
        out[plane + o] = h1;
    }
}

// Wp (N=256) + Ww (N=128) combined: grid.x = 12 (0..7 -> Wp, 8..11 -> Ww).
__global__ __launch_bounds__(256) void k_tsplit_pw(
    const float* __restrict__ Wp, const float* __restrict__ Ww,
    __half* __restrict__ out)
{
    __shared__ float t[32][33];
    const size_t plane = (size_t)NPW * ROI_DIM;
    const bool isW = blockIdx.x >= 8;
    const float* W = isW ? Ww : Wp;
    const int N = isW ? 128 : 256;
    const int rowOff = isW ? 256 : 0;
    const int nb = (isW ? (blockIdx.x - 8) : blockIdx.x) * 32;
    const int kb = blockIdx.y * 32;
    const int c = threadIdx.x & 31, r8 = threadIdx.x >> 5;
#pragma unroll
    for (int i = 0; i < 4; i++)
        t[r8 + i * 8][c] = W[(size_t)(kb + r8 + i * 8) * N + nb + c];
    __syncthreads();
#pragma unroll
    for (int i = 0; i < 4; i++) {
        const int n = nb + r8 + i * 8;
        const int k = kb + c;
        float x = t[c][r8 + i * 8] * WSCALE;
        __half h0, h1;
        h2split(x, h0, h1);
        size_t o = (size_t)(n + rowOff) * ROI_DIM + k;
        out[o] = h0;
        out[plane + o] = h1;
    }
}

// --------------------------- bilinear helper -------------------------------
__device__ __forceinline__ float bilin(const float* __restrict__ base,
                                       int Hl, int Wl, int stride,
                                       float y, float x)
{
    float fy = floorf(y), fx = floorf(x);
    int y0 = (int)fy, x0 = (int)fx;
    float wy1 = y - fy, wx1 = x - fx;
    float wy0 = 1.f - wy1, wx0 = 1.f - wx1;
    float v = 0.f;
    bool xa = (x0 >= 0) && (x0 < Wl);
    bool xb = (x0 + 1 >= 0) && (x0 + 1 < Wl);
    if (y0 >= 0 && y0 < Hl) {
        if (xa) v += base[(y0 * Wl + x0) * stride] * (wy0 * wx0);
        if (xb) v += base[(y0 * Wl + x0 + 1) * stride] * (wy0 * wx1);
    }
    if (y0 + 1 >= 0 && y0 + 1 < Hl) {
        if (xa) v += base[((y0 + 1) * Wl + x0) * stride] * (wy1 * wx0);
        if (xb) v += base[((y0 + 1) * Wl + x0 + 1) * stride] * (wy1 * wx1);
    }
    return v;
}

// ------------------- ROI align -> split fp16 planes -------------------------
__global__ __launch_bounds__(256) void k_roi(const float* __restrict__ ref,
                                             const float* __restrict__ value,
                                             __half* __restrict__ roiA)
{
    int q = blockIdx.x;
    int n = q / LQ;
    int t = threadIdx.x;
    __shared__ float sr[4];
    if (t < 4) sr[t] = ref[(size_t)q * 16 + t];
    __syncthreads();
    const float cx = sr[0], cy = sr[1], w = sr[2], h = sr[3];
    const float x1 = (cx - 0.5f * w) * 150.f - 0.5f;
    const float y1 = (cy - 0.5f * h) * 100.f - 0.5f;
    const float bw = w * 150.f / (float)ROI;
    const float bh = h * 100.f / (float)ROI;
    const float* base = value + (size_t)n * LEN_IN * CDIM + t;
    __half* out0 = roiA + (size_t)q * ROI_DIM;
    __half* out1 = out0 + (size_t)NQPAD * ROI_DIM;
    for (int by = 0; by < ROI; by++) {
        float y = y1 + bh * ((float)by + 0.5f);
        for (int bx = 0; bx < ROI; bx++) {
            float x = x1 + bw * ((float)bx + 0.5f);
            float v = bilin(base, 100, 150, CDIM, y, x);
            __half h0, h1;
            h2split(v, h0, h1);
            out0[(by * ROI + bx) * CDIM + t] = h0;
            out1[(by * ROI + bx) * CDIM + t] = h1;
        }
    }
}

// ---- fused: split-K reduce + bias + tanh/softmax + deformable sampling ----
__global__ __launch_bounds__(256) void k_sample(const float* __restrict__ ref,
                                                const float* __restrict__ part,
                                                const float* __restrict__ bp,
                                                const float* __restrict__ bw,
                                                const float* __restrict__ value,
                                                __half* __restrict__ attA)
{
    int q = blockIdx.x;
    int n = q / LQ;
    int t = threadIdx.x;
    int h = t >> 5, d = t & 31;
    __shared__ float s_pw[NPW];
    __shared__ float s_px[NHEADS][16];
    __shared__ float s_py[NHEADS][16];
    __shared__ float s_w[NHEADS][16];
    __shared__ float s_ref[16];

    // split-K reduction for this query row (same summation order as before)
    for (int j = t; j < NPW; j += 256) {
        float s = (j < 256) ? bp[j] : bw[j - 256];
        const float* p = part + (size_t)q * NPW + j;
#pragma unroll
        for (int z = 0; z < SPLITK; z++)
            s += p[(size_t)z * NQ * NPW];
        s_pw[j] = s;
    }
    if (t < 16) s_ref[t] = ref[(size_t)q * 16 + t];
    __syncthreads();

    if (t < 128) {
        int hh = t >> 4, lp = t & 15, l = lp >> 2;
        float ox = tanhf(s_pw[2 * t]);
        float oy = tanhf(s_pw[2 * t + 1]);
        s_px[hh][lp] = s_ref[l * 4 + 0] + ox * s_ref[l * 4 + 2] * 0.5f;
        s_py[hh][lp] = s_ref[l * 4 + 1] + oy * s_ref[l * 4 + 3] * 0.5f;
        s_w[hh][lp] = s_pw[256 + t];
    }
    __syncthreads();
    if (t < NHEADS) {
        float mx = -1e30f;
#pragma unroll
        for (int i = 0; i < 16; i++) mx = fmaxf(mx, s_w[t][i]);
        float sum = 0.f;
#pragma unroll
        for (int i = 0; i < 16; i++) {
            float e = expf(s_w[t][i] - mx);
            s_w[t][i] = e;
            sum += e;
        }
        float inv = 1.f / sum;
#pragma unroll
        for (int i = 0; i < 16; i++) s_w[t][i] *= inv;
    }
    __syncthreads();
    const int HL[4] = {100, 50, 25, 13};
    const int WL[4] = {150, 75, 38, 19};
    const int SL[4] = {0, 15000, 18750, 19700};
    float acc = 0.f;
#pragma unroll
    for (int l = 0; l < NLVL; l++) {
        const float* base =
            value + ((size_t)n * LEN_IN + SL[l]) * CDIM + h * DH + d;
#pragma unroll
        for (int p = 0; p < NPTS; p++) {
            int lp = l * 4 + p;
            float px = s_px[h][lp] * (float)WL[l] - 0.5f;
            float py = s_py[h][lp] * (float)HL[l] - 0.5f;
            acc += s_w[h][lp] * bilin(base, HL[l], WL[l], CDIM, py, px);
        }
    }
    __half h0, h1;
    h2split(acc, h0, h1);
    attA[(size_t)q * CDIM + t] = h0;
    attA[(size_t)NQPAD * CDIM + (size_t)q * CDIM + t] = h1;
}

// ------------------------------ launcher -----------------------------------
extern "C" void kernel_launch(void* const* d_in, const int* in_sizes, int n_in,
                              void* d_out, int out_size)
{
    (void)in_sizes; (void)n_in; (void)out_size;
    const float* ref  = (const float*)d_in[1];
    const float* flat = (const float*)d_in[2];
    const float* Wv   = (const float*)d_in[6];
    const float* bv   = (const float*)d_in[7];
    const float* Wp   = (const float*)d_in[8];
    const float* bp   = (const float*)d_in[9];
    const float* Ww   = (const float*)d_in[10];
    const float* bw   = (const float*)d_in[11];
    const float* Wo   = (const float*)d_in[12];
    const float* bo   = (const float*)d_in[13];
    float* out = (float*)d_out;

    float *p_value, *p_part;
    __half *p_roiA, *p_attA, *p_btv, *p_btpw, *p_btwo;
    cudaGetSymbolAddress((void**)&p_value, g_value);
    cudaGetSymbolAddress((void**)&p_roiA,  g_roiA);
    cudaGetSymbolAddress((void**)&p_attA,  g_attA);
    cudaGetSymbolAddress((void**)&p_part,  g_part);
    cudaGetSymbolAddress((void**)&p_btv,   g_btv);
    cudaGetSymbolAddress((void**)&p_btpw,  g_btpw);
    cudaGetSymbolAddress((void**)&p_btwo,  g_btwo);

    cudaFuncSetAttribute(mma_gemm, cudaFuncAttributeMaxDynamicSharedMemorySize,
                         SMEM_TOT);
    cudaFuncSetAttribute(mma_gemm_f32,
                         cudaFuncAttributeMaxDynamicSharedMemorySize, SMEM_TOT);

    // 0. weight transpose + x64 scale + fp16 split (2 launches)
    k_tsplit2<<<dim3(CDIM / 32, CDIM / 32, 2), 256>>>(Wv, p_btv, Wo, p_btwo);
    k_tsplit_pw<<<dim3(12, ROI_DIM / 32), 256>>>(Wp, Ww, p_btpw);

    // 1. value = input_flatten @ Wv + bv  (A split fused; grid 2 x 624)
    mma_gemm_f32<<<dim3(CDIM / 128, (MV + 127) / 128, 1), 256, SMEM_TOT>>>(
        flat, CDIM,
        p_btv, (size_t)CDIM * CDIM, CDIM,
        p_value, CDIM, MV, CDIM, bv, WSCALE_INV);

    // 2. ROI align -> split fp16 roi planes
    k_roi<<<NQ, 256>>>(ref, p_value, p_roiA);

    // 3. pw partials: roi @ [Wp | Ww]  (grid 3 x 10 x 28)
    mma_gemm<<<dim3(NPW / 128, NQPAD / 128, SPLITK), 256, SMEM_TOT>>>(
        p_roiA, (size_t)NQPAD * ROI_DIM, ROI_DIM,
        p_btpw, (size_t)NPW * ROI_DIM, ROI_DIM,
        p_part, NPW, (long long)NQ * NPW, NQ, KCHUNK, nullptr, WSCALE_INV);

    // 4. fused reduce + deformable sampling -> split fp16 att planes
    k_sample<<<NQ, 256>>>(ref, p_part, bp, bw, p_value, p_attA);

    // 5. out = att @ Wo + bo  (grid 2 x 10)
    mma_gemm<<<dim3(CDIM / 128, NQPAD / 128, 1), 256, SMEM_TOT>>>(
        p_attA, (size_t)NQPAD * CDIM, CDIM,
        p_btwo, (size_t)CDIM * CDIM, CDIM,
        out, CDIM, 0, NQ, CDIM, bo, WSCALE_INV);
}

// round 11
// speedup vs baseline: 1.3161x; 1.2630x over previous
#include <cuda_runtime.h>
#include <cuda_fp16.h>
#include <math.h>
#include <cstdint>

// ---------------------------------------------------------------------------
// MSMDDeformRegionAttn  (N=4, Lq=300, C=256, H=8, Dh=32, L=4, P=4, ROI=7)
//
//   1. value = input_flatten @ Wv + bv            (79788 x 256 x 256)  HMMA
//      (A-operand fp32 -> fp16x2 split fused into the GEMM A-load)
//   2. ROI-align 7x7 on level-0 feature map -> roi planes (fp16 split)
//      (position x channel-group parallel, float4 gathers, high MLP)
//   3. pw partials = roi_flat @ [Wp | Ww]         (1200 x 12544 x 384) HMMA
//   4. k_sample: split-K reduce + bias (fused) + tanh offsets + softmax
//      + deformable bilinear gather -> att planes
//   5. out = att @ Wo + bo                        (1200 x 256 x 256)   HMMA
//
// All GEMMs: mma.sync m16n8k16 fp16 with 2-way fp16 split of each fp32
// operand and 3 cross-products (00, 01, 10) -> residual ~2^-22. Weights
// pre-scaled x64 (epilogue x 1/64) to keep residuals in fp16 normal range.
// ---------------------------------------------------------------------------

#define NBATCH  4
#define LQ      300
#define NQ      (NBATCH * LQ)      // 1200
#define CDIM    256
#define NHEADS  8
#define DH      32
#define NLVL    4
#define NPTS    4
#define ROI     7
#define LEN_IN  19947
#define ROI_DIM (ROI * ROI * CDIM) // 12544
#define NPW     384                // 256 (Wp) + 128 (Ww)
#define SPLITK  28
#define KCHUNK  (ROI_DIM / SPLITK) // 448 = 14 * 32
#define MV      (NBATCH * LEN_IN)  // 79788
#define NQPAD   1280               // 10 * 128
#define WSCALE  64.0f
#define WSCALE_INV (1.0f / 64.0f)

// ------------------------- scratch (static device mem) ---------------------
__device__ float  g_value[(size_t)MV * CDIM];                  // 81.7 MB
__device__ __half g_roiA[(size_t)2 * NQPAD * ROI_DIM];         // 64.2 MB
__device__ __half g_attA[(size_t)2 * NQPAD * CDIM];            //  1.3 MB
__device__ float  g_part[(size_t)SPLITK * NQ * NPW];           // 51.6 MB
__device__ __half g_btv[(size_t)2 * CDIM * CDIM];
__device__ __half g_btpw[(size_t)2 * NPW * ROI_DIM];           // 19.3 MB
__device__ __half g_btwo[(size_t)2 * CDIM * CDIM];

// --------------------------- PTX primitives --------------------------------
__device__ __forceinline__ uint32_t smem_u32(const void* p)
{
    uint32_t a;
    asm("{ .reg .u64 t; cvta.to.shared.u64 t, %1; cvt.u32.u64 %0, t; }"
        : "=r"(a) : "l"(p));
    return a;
}
__device__ __forceinline__ void cp16(uint32_t dst, const void* src)
{
    asm volatile("cp.async.cg.shared.global [%0], [%1], 16;"
                 :: "r"(dst), "l"(src));
}
__device__ __forceinline__ void mma_f16(float* d, const uint32_t* a,
                                        const uint32_t* b)
{
    asm volatile(
        "mma.sync.aligned.m16n8k16.row.col.f32.f16.f16.f32 "
        "{%0,%1,%2,%3}, {%4,%5,%6,%7}, {%8,%9}, {%0,%1,%2,%3};"
        : "+f"(d[0]), "+f"(d[1]), "+f"(d[2]), "+f"(d[3])
        : "r"(a[0]), "r"(a[1]), "r"(a[2]), "r"(a[3]), "r"(b[0]), "r"(b[1]));
}
__device__ __forceinline__ void ldsm4(uint32_t* r, uint32_t addr)
{
    asm volatile(
        "ldmatrix.sync.aligned.m8n8.x4.shared.b16 {%0,%1,%2,%3}, [%4];"
        : "=r"(r[0]), "=r"(r[1]), "=r"(r[2]), "=r"(r[3]) : "r"(addr));
}

// --------------------------- fp16 2-way split -------------------------------
__device__ __forceinline__ void h2split(float x, __half& h0, __half& h1)
{
    h0 = __float2half_rn(x);
    h1 = __float2half_rn(x - __half2float(h0));
}

// ===== shared MMA compute core (128x128 tile, 8 warps 2x4, one k32 step) ====
#define MMA_STEP(aBase, bBase)                                                 \
    do {                                                                       \
        _Pragma("unroll")                                                      \
        for (int h = 0; h < 2; h++) {                                          \
            uint32_t bfr[2][4][2];                                             \
            _Pragma("unroll")                                                  \
            for (int pb = 0; pb < 2; pb++)                                     \
                _Pragma("unroll")                                              \
                for (int jj = 0; jj < 2; jj++) {                               \
                    uint32_t r[4];                                             \
                    ldsm4(r, sb + (bBase) + pb * 8192 + bOff + jj * 1024 +     \
                             ((((uint32_t)(h * 2) + bCk) ^ bSwz) << 4));       \
                    bfr[pb][jj * 2][0] = r[0]; bfr[pb][jj * 2][1] = r[1];      \
                    bfr[pb][jj * 2 + 1][0] = r[2];                             \
                    bfr[pb][jj * 2 + 1][1] = r[3];                             \
                }                                                              \
            _Pragma("unroll")                                                  \
            for (int pa = 0; pa < 2; pa++) {                                   \
                uint32_t af[4][4];                                             \
                _Pragma("unroll")                                              \
                for (int i = 0; i < 4; i++)                                    \
                    ldsm4(af[i], sb + (aBase) + pa * 8192 + aOff + i * 1024 +  \
                                 ((((uint32_t)(h * 2) + aCk) ^ aSwz) << 4));   \
                const int npb = 2 - pa;                                        \
                for (int pb = 0; pb < npb; pb++)                               \
                    _Pragma("unroll")                                          \
                    for (int i = 0; i < 4; i++)                                \
                        _Pragma("unroll")                                      \
                        for (int j = 0; j < 4; j++)                            \
                            mma_f16(acc[i][j], af[i], bfr[pb][j]);             \
            }                                                                  \
        }                                                                      \
    } while (0)

#define MMA_EPILOGUE()                                                         \
    do {                                                                       \
        const int colBase = n0 + warp_n * 32 + (lane & 3) * 2;                 \
        const int rowBase = m0 + warp_m * 64 + (lane >> 2);                    \
        _Pragma("unroll")                                                      \
        for (int i = 0; i < 4; i++) {                                          \
            _Pragma("unroll")                                                  \
            for (int j = 0; j < 4; j++) {                                      \
                const int gc = colBase + j * 8;                                \
                float bx = 0.f, by = 0.f;                                      \
                if (bias) { bx = bias[gc]; by = bias[gc + 1]; }                \
                const int r0 = rowBase + i * 16;                               \
                if (r0 < M) {                                                  \
                    float2 v = make_float2(acc[i][j][0] * outScale + bx,       \
                                           acc[i][j][1] * outScale + by);      \
                    *(float2*)(C + (size_t)r0 * ldc + gc) = v;                 \
                }                                                              \
                const int r1 = r0 + 8;                                         \
                if (r1 < M) {                                                  \
                    float2 v = make_float2(acc[i][j][2] * outScale + bx,       \
                                           acc[i][j][3] * outScale + by);      \
                    *(float2*)(C + (size_t)r1 * ldc + gc) = v;                 \
                }                                                              \
            }                                                                  \
        }                                                                      \
    } while (0)

#define MMA_LDSM_COORDS()                                                      \
    const uint32_t aRow = (uint32_t)(warp_m * 64 + (lane & 15));               \
    const uint32_t aOff = aRow * 64;                                           \
    const uint32_t aSwz = (aRow >> 1) & 3;                                     \
    const uint32_t aCk = (uint32_t)(lane >> 4);                                \
    const uint32_t bRow =                                                      \
        (uint32_t)(warp_n * 32 + ((lane >> 4) << 3) + (lane & 7));             \
    const uint32_t bOff = bRow * 64;                                           \
    const uint32_t bSwz = (bRow >> 1) & 3;                                     \
    const uint32_t bCk = (uint32_t)((lane >> 3) & 1)

#define SMEM_TOT 65536

// ------------- fp16x2 HMMA GEMM, A already split (pw / out GEMMs) ----------
__global__ __launch_bounds__(256, 2) void mma_gemm(
    const __half* __restrict__ Ap, size_t aPlane, int lda,
    const __half* __restrict__ Bp, size_t bPlane, int ldb,
    float* __restrict__ C, int ldc, long long cSplitStride,
    int M, int kChunkTot, const float* __restrict__ bias, float outScale)
{
    extern __shared__ __align__(16) char smc[];
    const uint32_t sb = smem_u32(smc);
    const int tid = threadIdx.x, lane = tid & 31, wid = tid >> 5;
    const int warp_m = wid >> 2, warp_n = wid & 3;
    const int m0 = blockIdx.y * 128, n0 = blockIdx.x * 128;
    const int kBase = blockIdx.z * kChunkTot;
    C += (long long)blockIdx.z * cSplitStride;

    const int lr = tid >> 2, lc = tid & 3;
    const uint32_t swz = (uint32_t)(lc ^ ((lr >> 1) & 3)) << 4;
    const uint32_t d1 = (uint32_t)lr * 64 + swz;
    const uint32_t d2 = d1 + 64 * 64;
    const __half* aS = Ap + (size_t)(m0 + lr) * lda + kBase + lc * 8;
    const __half* bS = Bp + (size_t)(n0 + lr) * ldb + kBase + lc * 8;

#define ISSUE(bo, ke)                                                          \
    do {                                                                       \
        cp16(sb + (bo) + d1, aS + (ke));                                       \
        cp16(sb + (bo) + 8192 + d1, aS + aPlane + (ke));                       \
        cp16(sb + (bo) + d2, aS + (size_t)64 * lda + (ke));                    \
        cp16(sb + (bo) + 8192 + d2, aS + aPlane + (size_t)64 * lda + (ke));    \
        cp16(sb + (bo) + 16384 + d1, bS + (ke));                               \
        cp16(sb + (bo) + 24576 + d1, bS + bPlane + (ke));                      \
        cp16(sb + (bo) + 16384 + d2, bS + (size_t)64 * ldb + (ke));            \
        cp16(sb + (bo) + 24576 + d2, bS + bPlane + (size_t)64 * ldb + (ke));   \
        asm volatile("cp.async.commit_group;" ::: "memory");                   \
    } while (0)

    MMA_LDSM_COORDS();

    float acc[4][4][4];
#pragma unroll
    for (int i = 0; i < 4; i++)
#pragma unroll
        for (int j = 0; j < 4; j++)
#pragma unroll
            for (int e = 0; e < 4; e++) acc[i][j][e] = 0.f;

    const int nIter = kChunkTot / 32;
    ISSUE(0u, 0);
    uint32_t bo = 0;
    for (int it = 0; it < nIter; it++) {
        asm volatile("cp.async.wait_group 0;" ::: "memory");
        __syncthreads();
        if (it + 1 < nIter) ISSUE(bo ^ 32768u, (it + 1) * 32);
        MMA_STEP(bo, bo + 16384);
        bo ^= 32768u;
    }
#undef ISSUE

    MMA_EPILOGUE();
}

// ------- fp16x2 HMMA GEMM, A fp32 with in-kernel split (value GEMM) --------
__global__ __launch_bounds__(256, 2) void mma_gemm_f32(
    const float* __restrict__ A, int lda,
    const __half* __restrict__ Bp, size_t bPlane, int ldb,
    float* __restrict__ C, int ldc,
    int M, int kChunkTot, const float* __restrict__ bias, float outScale)
{
    extern __shared__ __align__(16) char smc[];
    const uint32_t sb = smem_u32(smc);
    const int tid = threadIdx.x, lane = tid & 31, wid = tid >> 5;
    const int warp_m = wid >> 2, warp_n = wid & 3;
    const int m0 = blockIdx.y * 128, n0 = blockIdx.x * 128;

    const int row = tid >> 1;
    const int kh = (tid & 1) * 16;
    const bool aval = (m0 + row) < M;
    const float* aRowP = A + (size_t)(m0 + row) * lda + kh;
    const uint32_t sw = ((uint32_t)row >> 1) & 3;
    const uint32_t c0 = (uint32_t)(tid & 1) * 2;
    const uint32_t aoff0 = (uint32_t)row * 64 + ((c0 ^ sw) << 4);
    const uint32_t aoff1 = (uint32_t)row * 64 + (((c0 + 1) ^ sw) << 4);

    const int lr = tid >> 2, lc = tid & 3;
    const uint32_t swz = (uint32_t)(lc ^ ((lr >> 1) & 3)) << 4;
    const uint32_t d1 = (uint32_t)lr * 64 + swz;
    const uint32_t d2 = d1 + 64 * 64;
    const __half* bS = Bp + (size_t)(n0 + lr) * ldb + lc * 8;

#define ISSUEB(bo, ke)                                                         \
    do {                                                                       \
        cp16(sb + (bo) + d1, bS + (ke));                                       \
        cp16(sb + (bo) + 8192 + d1, bS + bPlane + (ke));                       \
        cp16(sb + (bo) + d2, bS + (size_t)64 * ldb + (ke));                    \
        cp16(sb + (bo) + 8192 + d2, bS + bPlane + (size_t)64 * ldb + (ke));    \
        asm volatile("cp.async.commit_group;" ::: "memory");                   \
    } while (0)

    MMA_LDSM_COORDS();

    float acc[4][4][4];
#pragma unroll
    for (int i = 0; i < 4; i++)
#pragma unroll
        for (int j = 0; j < 4; j++)
#pragma unroll
            for (int e = 0; e < 4; e++) acc[i][j][e] = 0.f;

    const int nIter = kChunkTot / 32;

    float fa[16];
#pragma unroll
    for (int j = 0; j < 4; j++) {
        float4 v = aval ? *(const float4*)(aRowP + j * 4)
                        : make_float4(0.f, 0.f, 0.f, 0.f);
        fa[j * 4 + 0] = v.x; fa[j * 4 + 1] = v.y;
        fa[j * 4 + 2] = v.z; fa[j * 4 + 3] = v.w;
    }
    ISSUEB(32768u, 0);

    for (int it = 0; it < nIter; it++) {
        {
            const uint32_t aBase = (uint32_t)(it & 1) * 16384u;
            unsigned short h0[16], h1[16];
#pragma unroll
            for (int e = 0; e < 16; e++) {
                __half a0, a1;
                h2split(fa[e], a0, a1);
                h0[e] = __half_as_ushort(a0);
                h1[e] = __half_as_ushort(a1);
            }
            uint4 q;
            q.x = (uint32_t)h0[0] | ((uint32_t)h0[1] << 16);
            q.y = (uint32_t)h0[2] | ((uint32_t)h0[3] << 16);
            q.z = (uint32_t)h0[4] | ((uint32_t)h0[5] << 16);
            q.w = (uint32_t)h0[6] | ((uint32_t)h0[7] << 16);
            *(uint4*)(smc + aBase + aoff0) = q;
            q.x = (uint32_t)h0[8] | ((uint32_t)h0[9] << 16);
            q.y = (uint32_t)h0[10] | ((uint32_t)h0[11] << 16);
            q.z = (uint32_t)h0[12] | ((uint32_t)h0[13] << 16);
            q.w = (uint32_t)h0[14] | ((uint32_t)h0[15] << 16);
            *(uint4*)(smc + aBase + aoff1) = q;
            q.x = (uint32_t)h1[0] | ((uint32_t)h1[1] << 16);
            q.y = (uint32_t)h1[2] | ((uint32_t)h1[3] << 16);
            q.z = (uint32_t)h1[4] | ((uint32_t)h1[5] << 16);
            q.w = (uint32_t)h1[6] | ((uint32_t)h1[7] << 16);
            *(uint4*)(smc + aBase + 8192 + aoff0) = q;
            q.x = (uint32_t)h1[8] | ((uint32_t)h1[9] << 16);
            q.y = (uint32_t)h1[10] | ((uint32_t)h1[11] << 16);
            q.z = (uint32_t)h1[12] | ((uint32_t)h1[13] << 16);
            q.w = (uint32_t)h1[14] | ((uint32_t)h1[15] << 16);
            *(uint4*)(smc + aBase + 8192 + aoff1) = q;
        }
        if (it + 1 < nIter) {
#pragma unroll
            for (int j = 0; j < 4; j++) {
                float4 v = aval
                    ? *(const float4*)(aRowP + (it + 1) * 32 + j * 4)
                    : make_float4(0.f, 0.f, 0.f, 0.f);
                fa[j * 4 + 0] = v.x; fa[j * 4 + 1] = v.y;
                fa[j * 4 + 2] = v.z; fa[j * 4 + 3] = v.w;
            }
        }
        asm volatile("cp.async.wait_group 0;" ::: "memory");
        __syncthreads();
        if (it + 1 < nIter)
            ISSUEB(32768u + (uint32_t)((it + 1) & 1) * 16384u, (it + 1) * 32);

        const uint32_t aBase = (uint32_t)(it & 1) * 16384u;
        const uint32_t bBase = 32768u + (uint32_t)(it & 1) * 16384u;
        MMA_STEP(aBase, bBase);
    }
#undef ISSUEB

    MMA_EPILOGUE();
}

// -------------- weight transpose + scale(x64) + fp16 2-way split ------------
__global__ __launch_bounds__(256) void k_tsplit2(
    const float* __restrict__ W0, __half* __restrict__ o0,
    const float* __restrict__ W1, __half* __restrict__ o1)
{
    __shared__ float t[32][33];
    const float* W = blockIdx.z ? W1 : W0;
    __half* out = blockIdx.z ? o1 : o0;
    const size_t plane = (size_t)CDIM * CDIM;
    const int kb = blockIdx.y * 32, nb = blockIdx.x * 32;
    const int c = threadIdx.x & 31, r8 = threadIdx.x >> 5;
#pragma unroll
    for (int i = 0; i < 4; i++)
        t[r8 + i * 8][c] = W[(size_t)(kb + r8 + i * 8) * CDIM + nb + c];
    __syncthreads();
#pragma unroll
    for (int i = 0; i < 4; i++) {
        const int n = nb + r8 + i * 8;
        const int k = kb + c;
        float x = t[c][r8 + i * 8] * WSCALE;
        __half h0, h1;
        h2split(x, h0, h1);
        size_t o = (size_t)n * CDIM + k;
        out[o] = h0;
        out[plane + o] = h1;
    }
}

__global__ __launch_bounds__(256) void k_tsplit_pw(
    const float* __restrict__ Wp, const float* __restrict__ Ww,
    __half* __restrict__ out)
{
    __shared__ float t[32][33];
    const size_t plane = (size_t)NPW * ROI_DIM;
    const bool isW = blockIdx.x >= 8;
    const float* W = isW ? Ww : Wp;
    const int N = isW ? 128 : 256;
    const int rowOff = isW ? 256 : 0;
    const int nb = (isW ? (blockIdx.x - 8) : blockIdx.x) * 32;
    const int kb = blockIdx.y * 32;
    const int c = threadIdx.x & 31, r8 = threadIdx.x >> 5;
#pragma unroll
    for (int i = 0; i < 4; i++)
        t[r8 + i * 8][c] = W[(size_t)(kb + r8 + i * 8) * N + nb + c];
    __syncthreads();
#pragma unroll
    for (int i = 0; i < 4; i++) {
        const int n = nb + r8 + i * 8;
        const int k = kb + c;
        float x = t[c][r8 + i * 8] * WSCALE;
        __half h0, h1;
        h2split(x, h0, h1);
        size_t o = (size_t)(n + rowOff) * ROI_DIM + k;
        out[o] = h0;
        out[plane + o] = h1;
    }
}

// --------------------------- bilinear helper (scalar) ----------------------
__device__ __forceinline__ float bilin(const float* __restrict__ base,
                                       int Hl, int Wl, int stride,
                                       float y, float x)
{
    float fy = floorf(y), fx = floorf(x);
    int y0 = (int)fy, x0 = (int)fx;
    float wy1 = y - fy, wx1 = x - fx;
    float wy0 = 1.f - wy1, wx0 = 1.f - wx1;
    float v = 0.f;
    bool xa = (x0 >= 0) && (x0 < Wl);
    bool xb = (x0 + 1 >= 0) && (x0 + 1 < Wl);
    if (y0 >= 0 && y0 < Hl) {
        if (xa) v += base[(y0 * Wl + x0) * stride] * (wy0 * wx0);
        if (xb) v += base[(y0 * Wl + x0 + 1) * stride] * (wy0 * wx1);
    }
    if (y0 + 1 >= 0 && y0 + 1 < Hl) {
        if (xa) v += base[((y0 + 1) * Wl + x0) * stride] * (wy1 * wx0);
        if (xb) v += base[((y0 + 1) * Wl + x0 + 1) * stride] * (wy1 * wx1);
    }
    return v;
}

// ------------------- ROI align -> split fp16 planes -------------------------
// Block (64, 8): tx = 4-channel group (float4 gathers), ty strides the 49
// bin positions. All gathers within a position are independent; positions
// per thread are independent -> high MLP, latency-hidden.
__global__ __launch_bounds__(512) void k_roi(const float* __restrict__ ref,
                                             const float* __restrict__ value,
                                             __half* __restrict__ roiA)
{
    const int q = blockIdx.x;
    const int n = q / LQ;
    const int tx = threadIdx.x;        // 0..63  -> channels tx*4 .. tx*4+3
    const int ty = threadIdx.y;        // 0..7   -> positions ty, ty+8, ...

    const float4 rp = *(const float4*)(ref + (size_t)q * 16);  // level-0 cx,cy,w,h
    const float x1 = (rp.x - 0.5f * rp.z) * 150.f - 0.5f;
    const float y1 = (rp.y - 0.5f * rp.w) * 100.f - 0.5f;
    const float bw = rp.z * 150.f / (float)ROI;
    const float bh = rp.w * 100.f / (float)ROI;

    const float* base = value + (size_t)n * LEN_IN * CDIM + tx * 4;
    __half* out0 = roiA + (size_t)q * ROI_DIM + tx * 4;
    __half* out1 = out0 + (size_t)NQPAD * ROI_DIM;

#pragma unroll
    for (int pos = ty; pos < ROI * ROI; pos += 8) {
        const int by = pos / ROI, bx = pos % ROI;
        const float y = y1 + bh * ((float)by + 0.5f);
        const float x = x1 + bw * ((float)bx + 0.5f);

        const float fy = floorf(y), fx = floorf(x);
        const int y0 = (int)fy, x0 = (int)fx;
        const float wy1 = y - fy, wx1 = x - fx;
        const float wy0 = 1.f - wy1, wx0 = 1.f - wx1;
        const bool ya = (y0 >= 0) && (y0 < 100);
        const bool yb = (y0 + 1 >= 0) && (y0 + 1 < 100);
        const bool xa = (x0 >= 0) && (x0 < 150);
        const bool xb = (x0 + 1 >= 0) && (x0 + 1 < 150);

        float4 v00 = make_float4(0.f, 0.f, 0.f, 0.f), v01 = v00,
               v10 = v00, v11 = v00;
        if (ya && xa) v00 = *(const float4*)(base + (size_t)(y0 * 150 + x0) * CDIM);
        if (ya && xb) v01 = *(const float4*)(base + (size_t)(y0 * 150 + x0 + 1) * CDIM);
        if (yb && xa) v10 = *(const float4*)(base + (size_t)((y0 + 1) * 150 + x0) * CDIM);
        if (yb && xb) v11 = *(const float4*)(base + (size_t)((y0 + 1) * 150 + x0 + 1) * CDIM);

        const float w00 = wy0 * wx0, w01 = wy0 * wx1;
        const float w10 = wy1 * wx0, w11 = wy1 * wx1;
        float o[4];
        o[0] = v00.x * w00 + v01.x * w01 + v10.x * w10 + v11.x * w11;
        o[1] = v00.y * w00 + v01.y * w01 + v10.y * w10 + v11.y * w11;
        o[2] = v00.z * w00 + v01.z * w01 + v10.z * w10 + v11.z * w11;
        o[3] = v00.w * w00 + v01.w * w01 + v10.w * w10 + v11.w * w11;

        unsigned short p0[4], p1[4];
#pragma unroll
        for (int e = 0; e < 4; e++) {
            __half a0, a1;
            h2split(o[e], a0, a1);
            p0[e] = __half_as_ushort(a0);
            p1[e] = __half_as_ushort(a1);
        }
        uint2 q0 = make_uint2((uint32_t)p0[0] | ((uint32_t)p0[1] << 16),
                              (uint32_t)p0[2] | ((uint32_t)p0[3] << 16));
        uint2 q1 = make_uint2((uint32_t)p1[0] | ((uint32_t)p1[1] << 16),
                              (uint32_t)p1[2] | ((uint32_t)p1[3] << 16));
        *(uint2*)(out0 + (size_t)pos * CDIM) = q0;
        *(uint2*)(out1 + (size_t)pos * CDIM) = q1;
    }
}

// ---- fused: split-K reduce + bias + tanh/softmax + deformable sampling ----
__global__ __launch_bounds__(256) void k_sample(const float* __restrict__ ref,
                                                const float* __restrict__ part,
                                                const float* __restrict__ bp,
                                                const float* __restrict__ bw,
                                                const float* __restrict__ value,
                                                __half* __restrict__ attA)
{
    int q = blockIdx.x;
    int n = q / LQ;
    int t = threadIdx.x;
    int h = t >> 5, d = t & 31;
    __shared__ float s_pw[NPW];
    __shared__ float s_px[NHEADS][16];
    __shared__ float s_py[NHEADS][16];
    __shared__ float s_w[NHEADS][16];
    __shared__ float s_ref[16];

    for (int j = t; j < NPW; j += 256) {
        float s = (j < 256) ? bp[j] : bw[j - 256];
        const float* p = part + (size_t)q * NPW + j;
#pragma unroll
        for (int z = 0; z < SPLITK; z++)
            s += p[(size_t)z * NQ * NPW];
        s_pw[j] = s;
    }
    if (t < 16) s_ref[t] = ref[(size_t)q * 16 + t];
    __syncthreads();

    if (t < 128) {
        int hh = t >> 4, lp = t & 15, l = lp >> 2;
        float ox = tanhf(s_pw[2 * t]);
        float oy = tanhf(s_pw[2 * t + 1]);
        s_px[hh][lp] = s_ref[l * 4 + 0] + ox * s_ref[l * 4 + 2] * 0.5f;
        s_py[hh][lp] = s_ref[l * 4 + 1] + oy * s_ref[l * 4 + 3] * 0.5f;
        s_w[hh][lp] = s_pw[256 + t];
    }
    __syncthreads();
    if (t < NHEADS) {
        float mx = -1e30f;
#pragma unroll
        for (int i = 0; i < 16; i++) mx = fmaxf(mx, s_w[t][i]);
        float sum = 0.f;
#pragma unroll
        for (int i = 0; i < 16; i++) {
            float e = expf(s_w[t][i] - mx);
            s_w[t][i] = e;
            sum += e;
        }
        float inv = 1.f / sum;
#pragma unroll
        for (int i = 0; i < 16; i++) s_w[t][i] *= inv;
    }
    __syncthreads();
    const int HL[4] = {100, 50, 25, 13};
    const int WL[4] = {150, 75, 38, 19};
    const int SL[4] = {0, 15000, 18750, 19700};
    float acc = 0.f;
#pragma unroll
    for (int l = 0; l < NLVL; l++) {
        const float* base =
            value + ((size_t)n * LEN_IN + SL[l]) * CDIM + h * DH + d;
#pragma unroll
        for (int p = 0; p < NPTS; p++) {
            int lp = l * 4 + p;
            float px = s_px[h][lp] * (float)WL[l] - 0.5f;
            float py = s_py[h][lp] * (float)HL[l] - 0.5f;
            acc += s_w[h][lp] * bilin(base, HL[l], WL[l], CDIM, py, px);
        }
    }
    __half h0, h1;
    h2split(acc, h0, h1);
    attA[(size_t)q * CDIM + t] = h0;
    attA[(size_t)NQPAD * CDIM + (size_t)q * CDIM + t] = h1;
}

// ------------------------------ launcher -----------------------------------
extern "C" void kernel_launch(void* const* d_in, const int* in_sizes, int n_in,
                              void* d_out, int out_size)
{
    (void)in_sizes; (void)n_in; (void)out_size;
    const float* ref  = (const float*)d_in[1];
    const float* flat = (const float*)d_in[2];
    const float* Wv   = (const float*)d_in[6];
    const float* bv   = (const float*)d_in[7];
    const float* Wp   = (const float*)d_in[8];
    const float* bp   = (const float*)d_in[9];
    const float* Ww   = (const float*)d_in[10];
    const float* bw   = (const float*)d_in[11];
    const float* Wo   = (const float*)d_in[12];
    const float* bo   = (const float*)d_in[13];
    float* out = (float*)d_out;

    float *p_value, *p_part;
    __half *p_roiA, *p_attA, *p_btv, *p_btpw, *p_btwo;
    cudaGetSymbolAddress((void**)&p_value, g_value);
    cudaGetSymbolAddress((void**)&p_roiA,  g_roiA);
    cudaGetSymbolAddress((void**)&p_attA,  g_attA);
    cudaGetSymbolAddress((void**)&p_part,  g_part);
    cudaGetSymbolAddress((void**)&p_btv,   g_btv);
    cudaGetSymbolAddress((void**)&p_btpw,  g_btpw);
    cudaGetSymbolAddress((void**)&p_btwo,  g_btwo);

    cudaFuncSetAttribute(mma_gemm, cudaFuncAttributeMaxDynamicSharedMemorySize,
                         SMEM_TOT);
    cudaFuncSetAttribute(mma_gemm_f32,
                         cudaFuncAttributeMaxDynamicSharedMemorySize, SMEM_TOT);

    // 0. weight transpose + x64 scale + fp16 split (2 launches)
    k_tsplit2<<<dim3(CDIM / 32, CDIM / 32, 2), 256>>>(Wv, p_btv, Wo, p_btwo);
    k_tsplit_pw<<<dim3(12, ROI_DIM / 32), 256>>>(Wp, Ww, p_btpw);

    // 1. value = input_flatten @ Wv + bv  (A split fused; grid 2 x 624)
    mma_gemm_f32<<<dim3(CDIM / 128, (MV + 127) / 128, 1), 256, SMEM_TOT>>>(
        flat, CDIM,
        p_btv, (size_t)CDIM * CDIM, CDIM,
        p_value, CDIM, MV, CDIM, bv, WSCALE_INV);

    // 2. ROI align -> split fp16 roi planes (position x channel parallel)
    k_roi<<<NQ, dim3(64, 8)>>>(ref, p_value, p_roiA);

    // 3. pw partials: roi @ [Wp | Ww]  (grid 3 x 10 x 28)
    mma_gemm<<<dim3(NPW / 128, NQPAD / 128, SPLITK), 256, SMEM_TOT>>>(
        p_roiA, (size_t)NQPAD * ROI_DIM, ROI_DIM,
        p_btpw, (size_t)NPW * ROI_DIM, ROI_DIM,
        p_part, NPW, (long long)NQ * NPW, NQ, KCHUNK, nullptr, WSCALE_INV);

    // 4. fused reduce + deformable sampling -> split fp16 att planes
    k_sample<<<NQ, 256>>>(ref, p_part, bp, bw, p_value, p_attA);

    // 5. out = att @ Wo + bo  (grid 2 x 10)
    mma_gemm<<<dim3(CDIM / 128, NQPAD / 128, 1), 256, SMEM_TOT>>>(
        p_attA, (size_t)NQPAD * CDIM, CDIM,
        p_btwo, (size_t)CDIM * CDIM, CDIM,
        out, CDIM, 0, NQ, CDIM, bo, WSCALE_INV);
}

// round 14
// speedup vs baseline: 1.3917x; 1.0574x over previous
#include <cuda_runtime.h>
#include <cuda_fp16.h>
#include <math.h>
#include <cstdint>

// ---------------------------------------------------------------------------
// MSMDDeformRegionAttn  (N=4, Lq=300, C=256, H=8, Dh=32, L=4, P=4, ROI=7)
//
//   1. value = input_flatten @ Wv + bv            (79788 x 256 x 256)  HMMA
//      (A-operand fp32 -> fp16x2 split fused into the GEMM A-load)
//   2. ROI-align 7x7 on level-0 feature map -> roi planes (fp16 split)
//      (per-position offsets/weights precomputed in smem; pure gather loop)
//   3. pw partials = roi_flat @ [Wp | Ww]         (1200 x 12544 x 384) HMMA
//   4. k_sample: split-K reduce + bias (fused) + tanh offsets + softmax
//      + deformable bilinear gather (precomputed offsets) -> att planes
//   5. out = att @ Wo + bo                        (1200 x 256 x 256)   HMMA
//
// All GEMMs: mma.sync m16n8k16 fp16 with 2-way fp16 split of each fp32
// operand and 3 cross-products (00, 01, 10) -> residual ~2^-22. Weights
// pre-scaled x64 (epilogue x 1/64) to keep residuals in fp16 normal range.
// ---------------------------------------------------------------------------

#define NBATCH  4
#define LQ      300
#define NQ      (NBATCH * LQ)      // 1200
#define CDIM    256
#define NHEADS  8
#define DH      32
#define NLVL    4
#define NPTS    4
#define ROI     7
#define LEN_IN  19947
#define ROI_DIM (ROI * ROI * CDIM) // 12544
#define NPW     384                // 256 (Wp) + 128 (Ww)
#define SPLITK  28
#define KCHUNK  (ROI_DIM / SPLITK) // 448 = 14 * 32
#define MV      (NBATCH * LEN_IN)  // 79788
#define NQPAD   1280               // 10 * 128
#define WSCALE  64.0f
#define WSCALE_INV (1.0f / 64.0f)

// ------------------------- scratch (static device mem) ---------------------
__device__ float  g_value[(size_t)MV * CDIM];                  // 81.7 MB
__device__ __half g_roiA[(size_t)2 * NQPAD * ROI_DIM];         // 64.2 MB
__device__ __half g_attA[(size_t)2 * NQPAD * CDIM];            //  1.3 MB
__device__ float  g_part[(size_t)SPLITK * NQ * NPW];           // 51.6 MB
__device__ __half g_btv[(size_t)2 * CDIM * CDIM];
__device__ __half g_btpw[(size_t)2 * NPW * ROI_DIM];           // 19.3 MB
__device__ __half g_btwo[(size_t)2 * CDIM * CDIM];

// --------------------------- PTX primitives --------------------------------
__device__ __forceinline__ uint32_t smem_u32(const void* p)
{
    uint32_t a;
    asm("{ .reg .u64 t; cvta.to.shared.u64 t, %1; cvt.u32.u64 %0, t; }"
        : "=r"(a) : "l"(p));
    return a;
}
__device__ __forceinline__ void cp16(uint32_t dst, const void* src)
{
    asm volatile("cp.async.cg.shared.global [%0], [%1], 16;"
                 :: "r"(dst), "l"(src));
}
__device__ __forceinline__ void mma_f16(float* d, const uint32_t* a,
                                        const uint32_t* b)
{
    asm volatile(
        "mma.sync.aligned.m16n8k16.row.col.f32.f16.f16.f32 "
        "{%0,%1,%2,%3}, {%4,%5,%6,%7}, {%8,%9}, {%0,%1,%2,%3};"
        : "+f"(d[0]), "+f"(d[1]), "+f"(d[2]), "+f"(d[3])
        : "r"(a[0]), "r"(a[1]), "r"(a[2]), "r"(a[3]), "r"(b[0]), "r"(b[1]));
}
__device__ __forceinline__ void ldsm4(uint32_t* r, uint32_t addr)
{
    asm volatile(
        "ldmatrix.sync.aligned.m8n8.x4.shared.b16 {%0,%1,%2,%3}, [%4];"
        : "=r"(r[0]), "=r"(r[1]), "=r"(r[2]), "=r"(r[3]) : "r"(addr));
}

// --------------------------- fp16 2-way split -------------------------------
__device__ __forceinline__ void h2split(float x, __half& h0, __half& h1)
{
    h0 = __float2half_rn(x);
    h1 = __float2half_rn(x - __half2float(h0));
}

// ===== shared MMA compute core (128x128 tile, 8 warps 2x4, one k32 step) ====
#define MMA_STEP(aBase, bBase)                                                 \
    do {                                                                       \
        _Pragma("unroll")                                                      \
        for (int h = 0; h < 2; h++) {                                          \
            uint32_t bfr[2][4][2];                                             \
            _Pragma("unroll")                                                  \
            for (int pb = 0; pb < 2; pb++)                                     \
                _Pragma("unroll")                                              \
                for (int jj = 0; jj < 2; jj++) {                               \
                    uint32_t r[4];                                             \
                    ldsm4(r, sb + (bBase) + pb * 8192 + bOff + jj * 1024 +     \
                             ((((uint32_t)(h * 2) + bCk) ^ bSwz) << 4));       \
                    bfr[pb][jj * 2][0] = r[0]; bfr[pb][jj * 2][1] = r[1];      \
                    bfr[pb][jj * 2 + 1][0] = r[2];                             \
                    bfr[pb][jj * 2 + 1][1] = r[3];                             \
                }                                                              \
            _Pragma("unroll")                                                  \
            for (int pa = 0; pa < 2; pa++) {                                   \
                uint32_t af[4][4];                                             \
                _Pragma("unroll")                                              \
                for (int i = 0; i < 4; i++)                                    \
                    ldsm4(af[i], sb + (aBase) + pa * 8192 + aOff + i * 1024 +  \
                                 ((((uint32_t)(h * 2) + aCk) ^ aSwz) << 4));   \
                const int npb = 2 - pa;                                        \
                for (int pb = 0; pb < npb; pb++)                               \
                    _Pragma("unroll")                                          \
                    for (int i = 0; i < 4; i++)                                \
                        _Pragma("unroll")                                      \
                        for (int j = 0; j < 4; j++)                            \
                            mma_f16(acc[i][j], af[i], bfr[pb][j]);             \
            }                                                                  \
        }                                                                      \
    } while (0)

#define MMA_EPILOGUE()                                                         \
    do {                                                                       \
        const int colBase = n0 + warp_n * 32 + (lane & 3) * 2;                 \
        const int rowBase = m0 + warp_m * 64 + (lane >> 2);                    \
        _Pragma("unroll")                                                      \
        for (int i = 0; i < 4; i++) {                                          \
            _Pragma("unroll")                                                  \
            for (int j = 0; j < 4; j++) {                                      \
                const int gc = colBase + j * 8;                                \
                float bx = 0.f, by = 0.f;                                      \
                if (bias) { bx = bias[gc]; by = bias[gc + 1]; }                \
                const int r0 = rowBase + i * 16;                               \
                if (r0 < M) {                                                  \
                    float2 v = make_float2(acc[i][j][0] * outScale + bx,       \
                                           acc[i][j][1] * outScale + by);      \
                    *(float2*)(C + (size_t)r0 * ldc + gc) = v;                 \
                }                                                              \
                const int r1 = r0 + 8;                                         \
                if (r1 < M) {                                                  \
                    float2 v = make_float2(acc[i][j][2] * outScale + bx,       \
                                           acc[i][j][3] * outScale + by);      \
                    *(float2*)(C + (size_t)r1 * ldc + gc) = v;                 \
                }                                                              \
            }                                                                  \
        }                                                                      \
    } while (0)

#define MMA_LDSM_COORDS()                                                      \
    const uint32_t aRow = (uint32_t)(warp_m * 64 + (lane & 15));               \
    const uint32_t aOff = aRow * 64;                                           \
    const uint32_t aSwz = (aRow >> 1) & 3;                                     \
    const uint32_t aCk = (uint32_t)(lane >> 4);                                \
    const uint32_t bRow =                                                      \
        (uint32_t)(warp_n * 32 + ((lane >> 4) << 3) + (lane & 7));             \
    const uint32_t bOff = bRow * 64;                                           \
    const uint32_t bSwz = (bRow >> 1) & 3;                                     \
    const uint32_t bCk = (uint32_t)((lane >> 3) & 1)

#define SMEM_TOT 65536

// ------------- fp16x2 HMMA GEMM, A already split (pw / out GEMMs) ----------
__global__ __launch_bounds__(256, 2) void mma_gemm(
    const __half* __restrict__ Ap, size_t aPlane, int lda,
    const __half* __restrict__ Bp, size_t bPlane, int ldb,
    float* __restrict__ C, int ldc, long long cSplitStride,
    int M, int kChunkTot, const float* __restrict__ bias, float outScale)
{
    extern __shared__ __align__(16) char smc[];
    const uint32_t sb = smem_u32(smc);
    const int tid = threadIdx.x, lane = tid & 31, wid = tid >> 5;
    const int warp_m = wid >> 2, warp_n = wid & 3;
    const int m0 = blockIdx.y * 128, n0 = blockIdx.x * 128;
    const int kBase = blockIdx.z * kChunkTot;
    C += (long long)blockIdx.z * cSplitStride;

    const int lr = tid >> 2, lc = tid & 3;
    const uint32_t swz = (uint32_t)(lc ^ ((lr >> 1) & 3)) << 4;
    const uint32_t d1 = (uint32_t)lr * 64 + swz;
    const uint32_t d2 = d1 + 64 * 64;
    const __half* aS = Ap + (size_t)(m0 + lr) * lda + kBase + lc * 8;
    const __half* bS = Bp + (size_t)(n0 + lr) * ldb + kBase + lc * 8;

#define ISSUE(bo, ke)                                                          \
    do {                                                                       \
        cp16(sb + (bo) + d1, aS + (ke));                                       \
        cp16(sb + (bo) + 8192 + d1, aS + aPlane + (ke));                       \
        cp16(sb + (bo) + d2, aS + (size_t)64 * lda + (ke));                    \
        cp16(sb + (bo) + 8192 + d2, aS + aPlane + (size_t)64 * lda + (ke));    \
        cp16(sb + (bo) + 16384 + d1, bS + (ke));                               \
        cp16(sb + (bo) + 24576 + d1, bS + bPlane + (ke));                      \
        cp16(sb + (bo) + 16384 + d2, bS + (size_t)64 * ldb + (ke));            \
        cp16(sb + (bo) + 24576 + d2, bS + bPlane + (size_t)64 * ldb + (ke));   \
        asm volatile("cp.async.commit_group;" ::: "memory");                   \
    } while (0)

    MMA_LDSM_COORDS();

    float acc[4][4][4];
#pragma unroll
    for (int i = 0; i < 4; i++)
#pragma unroll
        for (int j = 0; j < 4; j++)
#pragma unroll
            for (int e = 0; e < 4; e++) acc[i][j][e] = 0.f;

    const int nIter = kChunkTot / 32;
    ISSUE(0u, 0);
    uint32_t bo = 0;
    for (int it = 0; it < nIter; it++) {
        asm volatile("cp.async.wait_group 0;" ::: "memory");
        __syncthreads();
        if (it + 1 < nIter) ISSUE(bo ^ 32768u, (it + 1) * 32);
        MMA_STEP(bo, bo + 16384);
        bo ^= 32768u;
    }
#undef ISSUE

    MMA_EPILOGUE();
}

// ------- fp16x2 HMMA GEMM, A fp32 with in-kernel split (value GEMM) --------
__global__ __launch_bounds__(256, 2) void mma_gemm_f32(
    const float* __restrict__ A, int lda,
    const __half* __restrict__ Bp, size_t bPlane, int ldb,
    float* __restrict__ C, int ldc,
    int M, int kChunkTot, const float* __restrict__ bias, float outScale)
{
    extern __shared__ __align__(16) char smc[];
    const uint32_t sb = smem_u32(smc);
    const int tid = threadIdx.x, lane = tid & 31, wid = tid >> 5;
    const int warp_m = wid >> 2, warp_n = wid & 3;
    const int m0 = blockIdx.y * 128, n0 = blockIdx.x * 128;

    const int row = tid >> 1;
    const int kh = (tid & 1) * 16;
    const bool aval = (m0 + row) < M;
    const float* aRowP = A + (size_t)(m0 + row) * lda + kh;
    const uint32_t sw = ((uint32_t)row >> 1) & 3;
    const uint32_t c0 = (uint32_t)(tid & 1) * 2;
    const uint32_t aoff0 = (uint32_t)row * 64 + ((c0 ^ sw) << 4);
    const uint32_t aoff1 = (uint32_t)row * 64 + (((c0 + 1) ^ sw) << 4);

    const int lr = tid >> 2, lc = tid & 3;
    const uint32_t swz = (uint32_t)(lc ^ ((lr >> 1) & 3)) << 4;
    const uint32_t d1 = (uint32_t)lr * 64 + swz;
    const uint32_t d2 = d1 + 64 * 64;
    const __half* bS = Bp + (size_t)(n0 + lr) * ldb + lc * 8;

#define ISSUEB(bo, ke)                                                         \
    do {                                                                       \
        cp16(sb + (bo) + d1, bS + (ke));                                       \
        cp16(sb + (bo) + 8192 + d1, bS + bPlane + (ke));                       \
        cp16(sb + (bo) + d2, bS + (size_t)64 * ldb + (ke));                    \
        cp16(sb + (bo) + 8192 + d2, bS + bPlane + (size_t)64 * ldb + (ke));    \
        asm volatile("cp.async.commit_group;" ::: "memory");                   \
    } while (0)

    MMA_LDSM_COORDS();

    float acc[4][4][4];
#pragma unroll
    for (int i = 0; i < 4; i++)
#pragma unroll
        for (int j = 0; j < 4; j++)
#pragma unroll
            for (int e = 0; e < 4; e++) acc[i][j][e] = 0.f;

    const int nIter = kChunkTot / 32;

    float fa[16];
#pragma unroll
    for (int j = 0; j < 4; j++) {
        float4 v = aval ? *(const float4*)(aRowP + j * 4)
                        : make_float4(0.f, 0.f, 0.f, 0.f);
        fa[j * 4 + 0] = v.x; fa[j * 4 + 1] = v.y;
        fa[j * 4 + 2] = v.z; fa[j * 4 + 3] = v.w;
    }
    ISSUEB(32768u, 0);

    for (int it = 0; it < nIter; it++) {
        {
            const uint32_t aBase = (uint32_t)(it & 1) * 16384u;
            unsigned short h0[16], h1[16];
#pragma unroll
            for (int e = 0; e < 16; e++) {
                __half a0, a1;
                h2split(fa[e], a0, a1);
                h0[e] = __half_as_ushort(a0);
                h1[e] = __half_as_ushort(a1);
            }
            uint4 q;
            q.x = (uint32_t)h0[0] | ((uint32_t)h0[1] << 16);
            q.y = (uint32_t)h0[2] | ((uint32_t)h0[3] << 16);
            q.z = (uint32_t)h0[4] | ((uint32_t)h0[5] << 16);
            q.w = (uint32_t)h0[6] | ((uint32_t)h0[7] << 16);
            *(uint4*)(smc + aBase + aoff0) = q;
            q.x = (uint32_t)h0[8] | ((uint32_t)h0[9] << 16);
            q.y = (uint32_t)h0[10] | ((uint32_t)h0[11] << 16);
            q.z = (uint32_t)h0[12] | ((uint32_t)h0[13] << 16);
            q.w = (uint32_t)h0[14] | ((uint32_t)h0[15] << 16);
            *(uint4*)(smc + aBase + aoff1) = q;
            q.x = (uint32_t)h1[0] | ((uint32_t)h1[1] << 16);
            q.y = (uint32_t)h1[2] | ((uint32_t)h1[3] << 16);
            q.z = (uint32_t)h1[4] | ((uint32_t)h1[5] << 16);
            q.w = (uint32_t)h1[6] | ((uint32_t)h1[7] << 16);
            *(uint4*)(smc + aBase + 8192 + aoff0) = q;
            q.x = (uint32_t)h1[8] | ((uint32_t)h1[9] << 16);
            q.y = (uint32_t)h1[10] | ((uint32_t)h1[11] << 16);
            q.z = (uint32_t)h1[12] | ((uint32_t)h1[13] << 16);
            q.w = (uint32_t)h1[14] | ((uint32_t)h1[15] << 16);
            *(uint4*)(smc + aBase + 8192 + aoff1) = q;
        }
        if (it + 1 < nIter) {
#pragma unroll
            for (int j = 0; j < 4; j++) {
                float4 v = aval
                    ? *(const float4*)(aRowP + (it + 1) * 32 + j * 4)
                    : make_float4(0.f, 0.f, 0.f, 0.f);
                fa[j * 4 + 0] = v.x; fa[j * 4 + 1] = v.y;
                fa[j * 4 + 2] = v.z; fa[j * 4 + 3] = v.w;
            }
        }
        asm volatile("cp.async.wait_group 0;" ::: "memory");
        __syncthreads();
        if (it + 1 < nIter)
            ISSUEB(32768u + (uint32_t)((it + 1) & 1) * 16384u, (it + 1) * 32);

        const uint32_t aBase = (uint32_t)(it & 1) * 16384u;
        const uint32_t bBase = 32768u + (uint32_t)(it & 1) * 16384u;
        MMA_STEP(aBase, bBase);
    }
#undef ISSUEB

    MMA_EPILOGUE();
}

// -------------- weight transpose + scale(x64) + fp16 2-way split ------------
__global__ __launch_bounds__(256) void k_tsplit2(
    const float* __restrict__ W0, __half* __restrict__ o0,
    const float* __restrict__ W1, __half* __restrict__ o1)
{
    __shared__ float t[32][33];
    const float* W = blockIdx.z ? W1 : W0;
    __half* out = blockIdx.z ? o1 : o0;
    const size_t plane = (size_t)CDIM * CDIM;
    const int kb = blockIdx.y * 32, nb = blockIdx.x * 32;
    const int c = threadIdx.x & 31, r8 = threadIdx.x >> 5;
#pragma unroll
    for (int i = 0; i < 4; i++)
        t[r8 + i * 8][c] = W[(size_t)(kb + r8 + i * 8) * CDIM + nb + c];
    __syncthreads();
#pragma unroll
    for (int i = 0; i < 4; i++) {
        const int n = nb + r8 + i * 8;
        const int k = kb + c;
        float x = t[c][r8 + i * 8] * WSCALE;
        __half h0, h1;
        h2split(x, h0, h1);
        size_t o = (size_t)n * CDIM + k;
        out[o] = h0;
        out[plane + o] = h1;
    }
}

__global__ __launch_bounds__(256) void k_tsplit_pw(
    const float* __restrict__ Wp, const float* __restrict__ Ww,
    __half* __restrict__ out)
{
    __shared__ float t[32][33];
    const size_t plane = (size_t)NPW * ROI_DIM;
    const bool isW = blockIdx.x >= 8;
    const float* W = isW ? Ww : Wp;
    const int N = isW ? 128 : 256;
    const int rowOff = isW ? 256 : 0;
    const int nb = (isW ? (blockIdx.x - 8) : blockIdx.x) * 32;
    const int kb = blockIdx.y * 32;
    const int c = threadIdx.x & 31, r8 = threadIdx.x >> 5;
#pragma unroll
    for (int i = 0; i < 4; i++)
        t[r8 + i * 8][c] = W[(size_t)(kb + r8 + i * 8) * N + nb + c];
    __syncthreads();
#pragma unroll
    for (int i = 0; i < 4; i++) {
        const int n = nb + r8 + i * 8;
        const int k = kb + c;
        float x = t[c][r8 + i * 8] * WSCALE;
        __half h0, h1;
        h2split(x, h0, h1);
        size_t o = (size_t)(n + rowOff) * ROI_DIM + k;
        out[o] = h0;
        out[plane + o] = h1;
    }
}

// ------------------- ROI align -> split fp16 planes -------------------------
// Block (64, 8). Setup: threads 0..48 precompute per-position clamped corner
// element-offsets (int4) and validity-masked weights (float4) into smem.
// Main loop: pure smem-broadcast + float4 gather + FMA (bit-identical math:
// invalid corners contribute v_clamped * 0 == +/-0, absorbed by the sum).
__global__ __launch_bounds__(512) void k_roi(const float* __restrict__ ref,
                                             const float* __restrict__ value,
                                             __half* __restrict__ roiA)
{
    const int q = blockIdx.x;
    const int n = q / LQ;
    const int tx = threadIdx.x;        // 0..63 -> channels tx*4..tx*4+3
    const int ty = threadIdx.y;        // 0..7  -> positions ty, ty+8, ...
    const int tid = ty * 64 + tx;

    __shared__ int4  s_off[ROI * ROI];
    __shared__ float4 s_wt[ROI * ROI];

    if (tid < ROI * ROI) {
        const float4 rp = *(const float4*)(ref + (size_t)q * 16);
        const float x1 = (rp.x - 0.5f * rp.z) * 150.f - 0.5f;
        const float y1 = (rp.y - 0.5f * rp.w) * 100.f - 0.5f;
        const float bw = rp.z * 150.f / (float)ROI;
        const float bh = rp.w * 100.f / (float)ROI;
        const int by = tid / ROI, bx = tid % ROI;
        const float y = y1 + bh * ((float)by + 0.5f);
        const float x = x1 + bw * ((float)bx + 0.5f);
        const float fy = floorf(y), fx = floorf(x);
        const int y0 = (int)fy, x0 = (int)fx;
        const float wy1 = y - fy, wx1 = x - fx;
        const float wy0 = 1.f - wy1, wx0 = 1.f - wx1;
        const bool ya = (y0 >= 0) && (y0 < 100);
        const bool yb = (y0 + 1 >= 0) && (y0 + 1 < 100);
        const bool xa = (x0 >= 0) && (x0 < 150);
        const bool xb = (x0 + 1 >= 0) && (x0 + 1 < 150);
        const int yc0 = min(max(y0, 0), 99);
        const int yc1 = min(max(y0 + 1, 0), 99);
        const int xc0 = min(max(x0, 0), 149);
        const int xc1 = min(max(x0 + 1, 0), 149);
        s_off[tid] = make_int4((yc0 * 150 + xc0) * CDIM,
                               (yc0 * 150 + xc1) * CDIM,
                               (yc1 * 150 + xc0) * CDIM,
                               (yc1 * 150 + xc1) * CDIM);
        s_wt[tid] = make_float4((ya && xa) ? wy0 * wx0 : 0.f,
                                (ya && xb) ? wy0 * wx1 : 0.f,
                                (yb && xa) ? wy1 * wx0 : 0.f,
                                (yb && xb) ? wy1 * wx1 : 0.f);
    }
    __syncthreads();

    const float* base = value + (size_t)n * LEN_IN * CDIM + tx * 4;
    __half* out0 = roiA + (size_t)q * ROI_DIM + tx * 4;
    __half* out1 = out0 + (size_t)NQPAD * ROI_DIM;

#pragma unroll
    for (int pos = ty; pos < ROI * ROI; pos += 8) {
        const int4 off = s_off[pos];
        const float4 wt = s_wt[pos];
        const float4 v00 = *(const float4*)(base + off.x);
        const float4 v01 = *(const float4*)(base + off.y);
        const float4 v10 = *(const float4*)(base + off.z);
        const float4 v11 = *(const float4*)(base + off.w);

        float o[4];
        o[0] = v00.x * wt.x + v01.x * wt.y + v10.x * wt.z + v11.x * wt.w;
        o[1] = v00.y * wt.x + v01.y * wt.y + v10.y * wt.z + v11.y * wt.w;
        o[2] = v00.z * wt.x + v01.z * wt.y + v10.z * wt.z + v11.z * wt.w;
        o[3] = v00.w * wt.x + v01.w * wt.y + v10.w * wt.z + v11.w * wt.w;

        unsigned short p0[4], p1[4];
#pragma unroll
        for (int e = 0; e < 4; e++) {
            __half a0, a1;
            h2split(o[e], a0, a1);
            p0[e] = __half_as_ushort(a0);
            p1[e] = __half_as_ushort(a1);
        }
        uint2 q0 = make_uint2((uint32_t)p0[0] | ((uint32_t)p0[1] << 16),
                              (uint32_t)p0[2] | ((uint32_t)p0[3] << 16));
        uint2 q1 = make_uint2((uint32_t)p1[0] | ((uint32_t)p1[1] << 16),
                              (uint32_t)p1[2] | ((uint32_t)p1[3] << 16));
        *(uint2*)(out0 + (size_t)pos * CDIM) = q0;
        *(uint2*)(out1 + (size_t)pos * CDIM) = q1;
    }
}

// ---- fused: split-K reduce + bias + tanh/softmax + deformable sampling ----
// Gather offsets/weights precomputed per (head, level, point) by 128 threads;
// the 32 lanes of each head then do pure gathers (same FMA shapes as before).
__global__ __launch_bounds__(256) void k_sample(const float* __restrict__ ref,
                                                const float* __restrict__ part,
                                                const float* __restrict__ bp,
                                                const float* __restrict__ bw,
                                                const float* __restrict__ value,
                                                __half* __restrict__ attA)
{
    int q = blockIdx.x;
    int n = q / LQ;
    int t = threadIdx.x;
    int h = t >> 5, d = t & 31;
    __shared__ float s_pw[NPW];
    __shared__ float s_w[NHEADS][16];
    __shared__ float s_ref[16];
    __shared__ int4  s_goff[NHEADS][16];
    __shared__ float4 s_gw[NHEADS][16];

    // split-K reduction for this query row (same summation order as before)
    for (int j = t; j < NPW; j += 256) {
        float s = (j < 256) ? bp[j] : bw[j - 256];
        const float* p = part + (size_t)q * NPW + j;
#pragma unroll
        for (int z = 0; z < SPLITK; z++)
            s += p[(size_t)z * NQ * NPW];
        s_pw[j] = s;
    }
    if (t < 16) s_ref[t] = ref[(size_t)q * 16 + t];
    __syncthreads();

    if (t < 128) {
        const int HL[4] = {100, 50, 25, 13};
        const int WL[4] = {150, 75, 38, 19};
        const int SL[4] = {0, 15000, 18750, 19700};
        int hh = t >> 4, lp = t & 15, l = lp >> 2;
        float ox = tanhf(s_pw[2 * t]);
        float oy = tanhf(s_pw[2 * t + 1]);
        float pxn = s_ref[l * 4 + 0] + ox * s_ref[l * 4 + 2] * 0.5f;
        float pyn = s_ref[l * 4 + 1] + oy * s_ref[l * 4 + 3] * 0.5f;
        s_w[hh][lp] = s_pw[256 + t];

        // gather geometry (identical float expressions as the old gather)
        float px = pxn * (float)WL[l] - 0.5f;
        float py = pyn * (float)HL[l] - 0.5f;
        float fy = floorf(py), fx = floorf(px);
        int y0 = (int)fy, x0 = (int)fx;
        float wy1 = py - fy, wx1 = px - fx;
        float wy0 = 1.f - wy1, wx0 = 1.f - wx1;
        bool ya = (y0 >= 0) && (y0 < HL[l]);
        bool yb = (y0 + 1 >= 0) && (y0 + 1 < HL[l]);
        bool xa = (x0 >= 0) && (x0 < WL[l]);
        bool xb = (x0 + 1 >= 0) && (x0 + 1 < WL[l]);
        int yc0 = min(max(y0, 0), HL[l] - 1);
        int yc1 = min(max(y0 + 1, 0), HL[l] - 1);
        int xc0 = min(max(x0, 0), WL[l] - 1);
        int xc1 = min(max(x0 + 1, 0), WL[l] - 1);
        int baseOff = (n * LEN_IN + SL[l]) * CDIM + hh * DH;
        s_goff[hh][lp] = make_int4(baseOff + (yc0 * WL[l] + xc0) * CDIM,
                                   baseOff + (yc0 * WL[l] + xc1) * CDIM,
                                   baseOff + (yc1 * WL[l] + xc0) * CDIM,
                                   baseOff + (yc1 * WL[l] + xc1) * CDIM);
        s_gw[hh][lp] = make_float4((ya && xa) ? wy0 * wx0 : 0.f,
                                   (ya && xb) ? wy0 * wx1 : 0.f,
                                   (yb && xa) ? wy1 * wx0 : 0.f,
                                   (yb && xb) ? wy1 * wx1 : 0.f);
    }
    __syncthreads();
    if (t < NHEADS) {
        float mx = -1e30f;
#pragma unroll
        for (int i = 0; i < 16; i++) mx = fmaxf(mx, s_w[t][i]);
        float sum = 0.f;
#pragma unroll
        for (int i = 0; i < 16; i++) {
            float e = expf(s_w[t][i] - mx);
            s_w[t][i] = e;
            sum += e;
        }
        float inv = 1.f / sum;
#pragma unroll
        for (int i = 0; i < 16; i++) s_w[t][i] *= inv;
    }
    __syncthreads();

    float acc = 0.f;
#pragma unroll
    for (int lp = 0; lp < 16; lp++) {
        const int4 off = s_goff[h][lp];
        const float4 gw = s_gw[h][lp];
        float v00 = value[off.x + d];
        float v01 = value[off.y + d];
        float v10 = value[off.z + d];
        float v11 = value[off.w + d];
        float inner = v00 * gw.x + v01 * gw.y + v10 * gw.z + v11 * gw.w;
        acc += s_w[h][lp] * inner;
    }
    __half h0, h1;
    h2split(acc, h0, h1);
    attA[(size_t)q * CDIM + t] = h0;
    attA[(size_t)NQPAD * CDIM + (size_t)q * CDIM + t] = h1;
}

// ------------------------------ launcher -----------------------------------
extern "C" void kernel_launch(void* const* d_in, const int* in_sizes, int n_in,
                              void* d_out, int out_size)
{
    (void)in_sizes; (void)n_in; (void)out_size;
    const float* ref  = (const float*)d_in[1];
    const float* flat = (const float*)d_in[2];
    const float* Wv   = (const float*)d_in[6];
    const float* bv   = (const float*)d_in[7];
    const float* Wp   = (const float*)d_in[8];
    const float* bp   = (const float*)d_in[9];
    const float* Ww   = (const float*)d_in[10];
    const float* bw   = (const float*)d_in[11];
    const float* Wo   = (const float*)d_in[12];
    const float* bo   = (const float*)d_in[13];
    float* out = (float*)d_out;

    float *p_value, *p_part;
    __half *p_roiA, *p_attA, *p_btv, *p_btpw, *p_btwo;
    cudaGetSymbolAddress((void**)&p_value, g_value);
    cudaGetSymbolAddress((void**)&p_roiA,  g_roiA);
    cudaGetSymbolAddress((void**)&p_attA,  g_attA);
    cudaGetSymbolAddress((void**)&p_part,  g_part);
    cudaGetSymbolAddress((void**)&p_btv,   g_btv);
    cudaGetSymbolAddress((void**)&p_btpw,  g_btpw);
    cudaGetSymbolAddress((void**)&p_btwo,  g_btwo);

    cudaFuncSetAttribute(mma_gemm, cudaFuncAttributeMaxDynamicSharedMemorySize,
                         SMEM_TOT);
    cudaFuncSetAttribute(mma_gemm_f32,
                         cudaFuncAttributeMaxDynamicSharedMemorySize, SMEM_TOT);

    // 0. weight transpose + x64 scale + fp16 split (2 launches)
    k_tsplit2<<<dim3(CDIM / 32, CDIM / 32, 2), 256>>>(Wv, p_btv, Wo, p_btwo);
    k_tsplit_pw<<<dim3(12, ROI_DIM / 32), 256>>>(Wp, Ww, p_btpw);

    // 1. value = input_flatten @ Wv + bv  (A split fused; grid 2 x 624)
    mma_gemm_f32<<<dim3(CDIM / 128, (MV + 127) / 128, 1), 256, SMEM_TOT>>>(
        flat, CDIM,
        p_btv, (size_t)CDIM * CDIM, CDIM,
        p_value, CDIM, MV, CDIM, bv, WSCALE_INV);

    // 2. ROI align -> split fp16 roi planes (position x channel parallel)
    k_roi<<<NQ, dim3(64, 8)>>>(ref, p_value, p_roiA);

    // 3. pw partials: roi @ [Wp | Ww]  (grid 3 x 10 x 28)
    mma_gemm<<<dim3(NPW / 128, NQPAD / 128, SPLITK), 256, SMEM_TOT>>>(
        p_roiA, (size_t)NQPAD * ROI_DIM, ROI_DIM,
        p_btpw, (size_t)NPW * ROI_DIM, ROI_DIM,
        p_part, NPW, (long long)NQ * NPW, NQ, KCHUNK, nullptr, WSCALE_INV);

    // 4. fused reduce + deformable sampling -> split fp16 att planes
    k_sample<<<NQ, 256>>>(ref, p_part, bp, bw, p_value, p_attA);

    // 5. out = att @ Wo + bo  (grid 2 x 10)
    mma_gemm<<<dim3(CDIM / 128, NQPAD / 128, 1), 256, SMEM_TOT>>>(
        p_attA, (size_t)NQPAD * CDIM, CDIM,
        p_btwo, (size_t)CDIM * CDIM, CDIM,
        out, CDIM, 0, NQ, CDIM, bo, WSCALE_INV);
}